// round 3
// baseline (speedup 1.0000x reference)
#include <cuda_runtime.h>
#include <math.h>

// Problem constants
#define S_   1000
#define B_   64
#define D_   440
#define H_   512
#define O_   1000
#define SB_  64000
#define H3_  1536

// ---------------- scratch (static __device__) ----------------
__device__ __align__(16) float g_Wcat[H3_ * D_];          // packed [Wh;Wz;Wr] (1536 x 440)
__device__ __align__(16) float g_UzrT[H_ * 1024];         // [k][j]: j<512 -> Uz[j][k], else Ur[j-512][k]
__device__ __align__(16) float g_UhT[H_ * H_];            // [k][j] = Uh[j][k]
__device__ __align__(16) float g_Y[(size_t)SB_ * H3_];    // gate projections; BN-normalized in place
__device__ __align__(16) float g_Hst[(size_t)SB_ * H_];   // all hidden states h_t
__device__ float g_G1[H3_], g_B1[H3_];
__device__ float g_p1s[64 * H3_], g_p1q[64 * H3_];
__device__ float g_A1[H3_], g_C1[H3_];
__device__ float g_p2s[64 * O_], g_p2q[64 * O_];
__device__ float g_A2[O_], g_C2[O_];
__device__ __align__(16) float g_zrp[8][B_][1024];        // zr partials (current step)
__device__ __align__(16) float g_hcp[2][8][B_][H_];       // hcand partials, double-buffered
__device__ __align__(16) float g_z[2][B_][H_];            // combined z gate, double-buffered
__device__ unsigned g_barCount;
__device__ unsigned g_barEpoch;

// ---------------- fast grid barrier (release/acquire, no MEMBAR.GPU) ----------------
__device__ __forceinline__ void gbar() {
    __syncthreads();
    if (threadIdx.x == 0) {
        unsigned* pc; unsigned* pe;
        asm("cvta.global.u64 %0, %1;" : "=l"(pc) : "l"(&g_barCount));
        asm("cvta.global.u64 %0, %1;" : "=l"(pe) : "l"(&g_barEpoch));
        unsigned e = *((volatile unsigned*)pe);
        unsigned old;
        asm volatile("atom.add.release.gpu.global.u32 %0, [%1], 1;"
                     : "=r"(old) : "l"(pc) : "memory");
        if (old == 127u) {
            asm volatile("st.relaxed.gpu.global.u32 [%0], %1;" :: "l"(pc), "r"(0u) : "memory");
            asm volatile("st.release.gpu.global.u32 [%0], %1;" :: "l"(pe), "r"(e + 1u) : "memory");
        } else {
            unsigned cur;
            do {
                asm volatile("ld.acquire.gpu.global.u32 %0, [%1];"
                             : "=r"(cur) : "l"(pe) : "memory");
            } while (cur == e);
        }
    }
    __syncthreads();
}

// ---------------- weight packing ----------------
__global__ void pack_w(const float* __restrict__ Wh, const float* __restrict__ Wz,
                       const float* __restrict__ Wr) {
    int i = blockIdx.x * 256 + threadIdx.x;
    int j = i / D_, k = i - j * D_;
    float v = (j < 512) ? Wh[j * D_ + k] : (j < 1024) ? Wz[(j - 512) * D_ + k]
                                                      : Wr[(j - 1024) * D_ + k];
    g_Wcat[i] = v;
}

__global__ void pack_u(const float* __restrict__ Uh, const float* __restrict__ Uz,
                       const float* __restrict__ Ur) {
    int i = blockIdx.x * 256 + threadIdx.x;
    if (i < H_ * 1024) {
        int k = i >> 10, j = i & 1023;
        g_UzrT[i] = (j < 512) ? Uz[j * H_ + k] : Ur[(j - 512) * H_ + k];
    } else {
        int i2 = i - H_ * 1024;
        int k = i2 >> 9, j = i2 & 511;
        g_UhT[i2] = Uh[j * H_ + k];
    }
}

__global__ void pack_gb(const float* __restrict__ gh, const float* __restrict__ bh,
                        const float* __restrict__ gz, const float* __restrict__ bz,
                        const float* __restrict__ gr, const float* __restrict__ br) {
    int i = blockIdx.x * 256 + threadIdx.x;
    float g, b;
    if (i < 512)      { g = gh[i];        b = bh[i]; }
    else if (i < 1024){ g = gz[i - 512];  b = bz[i - 512]; }
    else              { g = gr[i - 1024]; b = br[i - 1024]; }
    g_G1[i] = g; g_B1[i] = b;
}

// ---------------- fp32 SGEMM: C[M,N] = A[M,K] * Bw[N,K]^T ----------------
#define GBM 128
#define GBN 64
#define GBK 8
__global__ __launch_bounds__(256) void sgemm_kernel(
    const float* __restrict__ A, const float* __restrict__ Bw, float* __restrict__ C,
    int M, int N, int K, int ldc) {
    __shared__ float As[2][GBK][GBM + 4];
    __shared__ float Bs[2][GBK][GBN + 4];
    const int bm = blockIdx.y * GBM;
    const int bn = blockIdx.x * GBN;
    const int t  = threadIdx.x;
    const int tx = t & 15;
    const int ty = t >> 4;
    const int lam = t >> 1, lak = (t & 1) * 4;
    const int lbn = (t & 127) >> 1, lbk = (t & 1) * 4;
    const bool bload = t < 128;

    float acc[8][4];
#pragma unroll
    for (int i = 0; i < 8; i++)
#pragma unroll
        for (int j = 0; j < 4; j++) acc[i][j] = 0.f;

    const int nt = K / GBK;
    float4 va, vb;
    va = *(const float4*)(A + (size_t)(bm + lam) * K + lak);
    vb = make_float4(0.f, 0.f, 0.f, 0.f);
    if (bload && (bn + lbn) < N) vb = *(const float4*)(Bw + (size_t)(bn + lbn) * K + lbk);
    As[0][lak + 0][lam] = va.x; As[0][lak + 1][lam] = va.y;
    As[0][lak + 2][lam] = va.z; As[0][lak + 3][lam] = va.w;
    if (bload) {
        Bs[0][lbk + 0][lbn] = vb.x; Bs[0][lbk + 1][lbn] = vb.y;
        Bs[0][lbk + 2][lbn] = vb.z; Bs[0][lbk + 3][lbn] = vb.w;
    }
    __syncthreads();

    for (int kt = 0; kt < nt; kt++) {
        const int cur = kt & 1;
        const bool has = (kt + 1) < nt;
        if (has) {
            const int k0 = (kt + 1) * GBK;
            va = *(const float4*)(A + (size_t)(bm + lam) * K + k0 + lak);
            vb = make_float4(0.f, 0.f, 0.f, 0.f);
            if (bload && (bn + lbn) < N)
                vb = *(const float4*)(Bw + (size_t)(bn + lbn) * K + k0 + lbk);
        }
#pragma unroll
        for (int k = 0; k < GBK; k++) {
            float a[8], b[4];
#pragma unroll
            for (int i = 0; i < 8; i++) a[i] = As[cur][k][ty * 8 + i];
#pragma unroll
            for (int j = 0; j < 4; j++) b[j] = Bs[cur][k][tx * 4 + j];
#pragma unroll
            for (int i = 0; i < 8; i++)
#pragma unroll
                for (int j = 0; j < 4; j++)
                    acc[i][j] = fmaf(a[i], b[j], acc[i][j]);
        }
        if (has) {
            const int nb = cur ^ 1;
            As[nb][lak + 0][lam] = va.x; As[nb][lak + 1][lam] = va.y;
            As[nb][lak + 2][lam] = va.z; As[nb][lak + 3][lam] = va.w;
            if (bload) {
                Bs[nb][lbk + 0][lbn] = vb.x; Bs[nb][lbk + 1][lbn] = vb.y;
                Bs[nb][lbk + 2][lbn] = vb.z; Bs[nb][lbk + 3][lbn] = vb.w;
            }
        }
        __syncthreads();
    }

#pragma unroll
    for (int i = 0; i < 8; i++) {
        const size_t m = (size_t)(bm + ty * 8 + i);
#pragma unroll
        for (int j = 0; j < 4; j++) {
            const int n = bn + tx * 4 + j;
            if (n < N) C[m * ldc + n] = acc[i][j];
        }
    }
}

// ---------------- deterministic column stats ----------------
__global__ void colstat_stage1(const float* __restrict__ X, int ncols,
                               float* __restrict__ ps, float* __restrict__ pq) {
    const int col = blockIdx.x * 256 + threadIdx.x;
    if (col >= ncols) return;
    const int chunk = blockIdx.y;
    const size_t base = (size_t)chunk * 1000 * ncols + col;
    float s = 0.f, q = 0.f;
    for (int r = 0; r < 1000; r++) {
        const float v = X[base + (size_t)r * ncols];
        s += v; q = fmaf(v, v, q);
    }
    ps[chunk * ncols + col] = s;
    pq[chunk * ncols + col] = q;
}

__global__ void colstat_stage2(const float* __restrict__ ps, const float* __restrict__ pq,
                               int ncols, const float* __restrict__ gamma,
                               const float* __restrict__ beta,
                               float* __restrict__ Aout, float* __restrict__ Cout) {
    const int col = blockIdx.x * 256 + threadIdx.x;
    if (col >= ncols) return;
    float s = 0.f, q = 0.f;
    for (int c = 0; c < 64; c++) { s += ps[c * ncols + col]; q += pq[c * ncols + col]; }
    const float m = s * (1.f / 64000.f);
    const float v = q * (1.f / 64000.f) - m * m;
    const float a = gamma[col] * rsqrtf(v + 1e-5f);
    Aout[col] = a;
    Cout[col] = beta[col] - m * a;
}

// fold BN into Y in place: y = y*A1[col] + C1[col]
__global__ void bnapply_Y() {
    const size_t i = (size_t)blockIdx.x * 256 + threadIdx.x;   // < 64000*1536
    const int col = (int)(i % H3_);
    g_Y[i] = fmaf(g_Y[i], g_A1[col], g_C1[col]);
}

// ---------------- persistent GRU scan v2: 128 CTAs x 256 threads ----------------
// smem: sU1[64][64] (Uzr slice), sU2[64][32] (Uh slice), sH1[64][64], sH2[64][64], sRH[64][64]
#define SM_U1 0
#define SM_U2 4096
#define SM_H1 6144
#define SM_H2 10240
#define SM_RH 14336
#define SM_TOT_FLOATS 18432

__global__ __launch_bounds__(256, 1) void scan2_kernel() {
    extern __shared__ float sm[];
    float* sU1 = sm + SM_U1;
    float* sU2 = sm + SM_U2;
    float* sH1 = sm + SM_H1;
    float* sH2 = sm + SM_H2;
    float* sRH = sm + SM_RH;

    const int cta = blockIdx.x;
    const int tid = threadIdx.x;
    const int jt = cta & 15;     // p1: 64-wide j tile of 1024; p2: 32-wide j tile of 512
    const int kg = cta >> 4;     // both phases: 64-wide k group (8 groups)

    // stage U slices into smem (persistent for all 1000 steps)
    for (int i = tid; i < 4096; i += 256) {
        const int kk = i >> 6, jj = i & 63;
        sU1[i] = g_UzrT[(kg * 64 + kk) * 1024 + jt * 64 + jj];
    }
    for (int i = tid; i < 2048; i += 256) {
        const int kk = i >> 5, jj = i & 31;
        sU2[i] = g_UhT[(kg * 64 + kk) * 512 + jt * 32 + jj];
    }
    for (int i = tid; i < 4096; i += 256) { sH1[i] = 0.f; sH2[i] = 0.f; }
    __syncthreads();

    // p1 gemm mapping: 4b x 4j per thread
    const int tx = tid & 15, ty = tid >> 4;
    const int j0 = tx * 4, b0 = ty * 4;
    // p2 gemm mapping: 8b x 1j per thread
    const int w = tid >> 5, lane = tid & 31;
    const int b0p2 = w * 8;

    for (int t = 0; t < S_; t++) {
        const int ob = (t & 1) ^ 1;   // buffers written at step t-1
        const int nb = t & 1;

        // ---- P1 stage: fold in h_{t-1} = z*h + (1-z)*hcand for this CTA's k cols ----
        if (t > 0) {
            const float* Yp = g_Y + (size_t)(t - 1) * B_ * H3_;
#pragma unroll 4
            for (int e = 0; e < 16; e++) {
                const int idx = e * 256 + tid;
                const int b = idx >> 6, kk = idx & 63;
                const int col = kg * 64 + kk;
                float hc = 0.f;
#pragma unroll
                for (int g = 0; g < 8; g++) hc += g_hcp[ob][g][b][col];
                hc = tanhf(Yp[b * H3_ + col] + hc);
                const float z = g_z[ob][b][col];
                const float hn = fmaf(z, sH1[b * 64 + kk] - hc, hc);
                sH1[b * 64 + kk] = hn;
                if (jt == 0)
                    g_Hst[((size_t)(t - 1) * B_ + b) * H_ + col] = hn;
            }
        }
        __syncthreads();

        // ---- P1 gemm: zr partials = sH1 . sU1 ----
        {
            float acc[4][4];
#pragma unroll
            for (int i = 0; i < 4; i++)
#pragma unroll
                for (int j = 0; j < 4; j++) acc[i][j] = 0.f;
#pragma unroll 4
            for (int kk = 0; kk < 64; kk += 4) {
                float4 hb[4], uq[4];
#pragma unroll
                for (int i = 0; i < 4; i++)
                    hb[i] = *(const float4*)&sH1[(b0 + i) * 64 + kk];
#pragma unroll
                for (int q = 0; q < 4; q++)
                    uq[q] = *(const float4*)&sU1[(kk + q) * 64 + j0];
#pragma unroll
                for (int i = 0; i < 4; i++) {
#pragma unroll
                    for (int q = 0; q < 4; q++) {
                        const float hv = (q == 0) ? hb[i].x : (q == 1) ? hb[i].y
                                        : (q == 2) ? hb[i].z : hb[i].w;
                        acc[i][0] = fmaf(hv, uq[q].x, acc[i][0]);
                        acc[i][1] = fmaf(hv, uq[q].y, acc[i][1]);
                        acc[i][2] = fmaf(hv, uq[q].z, acc[i][2]);
                        acc[i][3] = fmaf(hv, uq[q].w, acc[i][3]);
                    }
                }
            }
#pragma unroll
            for (int i = 0; i < 4; i++)
                *(float4*)&g_zrp[kg][b0 + i][jt * 64 + j0] =
                    make_float4(acc[i][0], acc[i][1], acc[i][2], acc[i][3]);
        }
        gbar();

        // ---- P2 stage: update sH2 (h_{t-1}), compute r & rh; combine z_t ----
        {
            const float* Yt = g_Y + (size_t)t * B_ * H3_;
            const float* Yp = g_Y + (size_t)(t - 1) * B_ * H3_;
#pragma unroll 2
            for (int e = 0; e < 16; e++) {
                const int idx = e * 256 + tid;
                const int b = idx >> 6, kk = idx & 63;
                const int col = kg * 64 + kk;
                float h = 0.f;
                if (t > 0) {
                    float hc = 0.f;
#pragma unroll
                    for (int g = 0; g < 8; g++) hc += g_hcp[ob][g][b][col];
                    hc = tanhf(Yp[b * H3_ + col] + hc);
                    const float z = g_z[ob][b][col];
                    h = fmaf(z, sH2[b * 64 + kk] - hc, hc);
                    sH2[b * 64 + kk] = h;
                }
                float rp = 0.f;
#pragma unroll
                for (int g = 0; g < 8; g++) rp += g_zrp[g][b][512 + col];
                const float r = 1.f / (1.f + __expf(-(Yt[b * H3_ + 1024 + col] + rp)));
                sRH[b * 64 + kk] = r * h;
            }
            // z combine (1 elem per thread, 256 per CTA)
            const int gidx = cta * 256 + tid;
            const int zb = gidx >> 9, zj = gidx & 511;
            float zp = 0.f;
#pragma unroll
            for (int g = 0; g < 8; g++) zp += g_zrp[g][zb][zj];
            g_z[nb][zb][zj] = 1.f / (1.f + __expf(-(Yt[zb * H3_ + 512 + zj] + zp)));
        }
        __syncthreads();

        // ---- P2 gemm: hcand partials = sRH . sU2 ----
        {
            float a2[8];
#pragma unroll
            for (int i = 0; i < 8; i++) a2[i] = 0.f;
#pragma unroll 4
            for (int kk = 0; kk < 64; kk += 4) {
                float4 rb[8];
#pragma unroll
                for (int i = 0; i < 8; i++)
                    rb[i] = *(const float4*)&sRH[(b0p2 + i) * 64 + kk];
                float u0 = sU2[(kk + 0) * 32 + lane];
                float u1 = sU2[(kk + 1) * 32 + lane];
                float u2 = sU2[(kk + 2) * 32 + lane];
                float u3 = sU2[(kk + 3) * 32 + lane];
#pragma unroll
                for (int i = 0; i < 8; i++) {
                    a2[i] = fmaf(rb[i].x, u0, a2[i]);
                    a2[i] = fmaf(rb[i].y, u1, a2[i]);
                    a2[i] = fmaf(rb[i].z, u2, a2[i]);
                    a2[i] = fmaf(rb[i].w, u3, a2[i]);
                }
            }
            const int jg = jt * 32 + lane;
#pragma unroll
            for (int i = 0; i < 8; i++)
                g_hcp[nb][kg][b0p2 + i][jg] = a2[i];
        }
        gbar();
    }

    // ---- final: h_999 (uses z/hcp written at step 999, buffer 1) ----
    if (jt == 0) {
        const float* Yl = g_Y + (size_t)(S_ - 1) * B_ * H3_;
#pragma unroll 4
        for (int e = 0; e < 16; e++) {
            const int idx = e * 256 + tid;
            const int b = idx >> 6, kk = idx & 63;
            const int col = kg * 64 + kk;
            float hc = 0.f;
#pragma unroll
            for (int g = 0; g < 8; g++) hc += g_hcp[1][g][b][col];
            hc = tanhf(Yl[b * H3_ + col] + hc);
            const float z = g_z[1][b][col];
            g_Hst[((size_t)(S_ - 1) * B_ + b) * H_ + col] =
                fmaf(z, sH1[b * 64 + kk] - hc, hc);
        }
    }
}

// ---------------- row log_softmax with folded BN, in place ----------------
__global__ __launch_bounds__(256) void logsoftmax_kernel(float* __restrict__ C) {
    const int row = blockIdx.x;
    float* p = C + (size_t)row * O_;
    __shared__ float red[256];
    const int t = threadIdx.x;
    float mx = -3.4e38f;
    for (int j = t; j < O_; j += 256) {
        const float v = p[j] * g_A2[j] + g_C2[j];
        mx = fmaxf(mx, v);
    }
    red[t] = mx; __syncthreads();
    for (int s = 128; s > 0; s >>= 1) { if (t < s) red[t] = fmaxf(red[t], red[t + s]); __syncthreads(); }
    mx = red[0]; __syncthreads();
    float sum = 0.f;
    for (int j = t; j < O_; j += 256) {
        const float v = p[j] * g_A2[j] + g_C2[j];
        sum += expf(v - mx);
    }
    red[t] = sum; __syncthreads();
    for (int s = 128; s > 0; s >>= 1) { if (t < s) red[t] += red[t + s]; __syncthreads(); }
    const float lse = mx + logf(red[0]);
    __syncthreads();
    for (int j = t; j < O_; j += 256) {
        const float v = p[j] * g_A2[j] + g_C2[j];
        p[j] = v - lse;
    }
}

// ---------------- launch ----------------
extern "C" void kernel_launch(void* const* d_in, const int* in_sizes, int n_in,
                              void* d_out, int out_size) {
    const float* x  = (const float*)d_in[0];
    const float* Wh = (const float*)d_in[1];
    const float* Wz = (const float*)d_in[2];
    const float* Wr = (const float*)d_in[3];
    const float* Uh = (const float*)d_in[4];
    const float* Uz = (const float*)d_in[5];
    const float* Ur = (const float*)d_in[6];
    const float* gh = (const float*)d_in[7];
    const float* bh = (const float*)d_in[8];
    const float* gz = (const float*)d_in[9];
    const float* bz = (const float*)d_in[10];
    const float* gr = (const float*)d_in[11];
    const float* br = (const float*)d_in[12];
    const float* Wf = (const float*)d_in[13];
    const float* gf = (const float*)d_in[14];
    const float* bf = (const float*)d_in[15];
    float* out = (float*)d_out;

    float *pY, *pH, *pWcat, *p1s, *p1q, *p2s, *p2q, *pG1, *pB1, *pA1, *pC1, *pA2, *pC2;
    cudaGetSymbolAddress((void**)&pY,    g_Y);
    cudaGetSymbolAddress((void**)&pH,    g_Hst);
    cudaGetSymbolAddress((void**)&pWcat, g_Wcat);
    cudaGetSymbolAddress((void**)&p1s,   g_p1s);
    cudaGetSymbolAddress((void**)&p1q,   g_p1q);
    cudaGetSymbolAddress((void**)&p2s,   g_p2s);
    cudaGetSymbolAddress((void**)&p2q,   g_p2q);
    cudaGetSymbolAddress((void**)&pG1,   g_G1);
    cudaGetSymbolAddress((void**)&pB1,   g_B1);
    cudaGetSymbolAddress((void**)&pA1,   g_A1);
    cudaGetSymbolAddress((void**)&pC1,   g_C1);
    cudaGetSymbolAddress((void**)&pA2,   g_A2);
    cudaGetSymbolAddress((void**)&pC2,   g_C2);

    static int smem_set = 0;
    if (!smem_set) {
        cudaFuncSetAttribute(scan2_kernel, cudaFuncAttributeMaxDynamicSharedMemorySize,
                             SM_TOT_FLOATS * (int)sizeof(float));
        smem_set = 1;
    }

    // 1) pack weights
    pack_w <<<2640, 256>>>(Wh, Wz, Wr);
    pack_u <<<3072, 256>>>(Uh, Uz, Ur);
    pack_gb<<<6,    256>>>(gh, bh, gz, bz, gr, br);

    // 2) gate projections: Y = x @ Wcat^T
    sgemm_kernel<<<dim3(H3_ / GBN, SB_ / GBM), 256>>>(x, pWcat, pY, SB_, H3_, D_, H3_);

    // 3) BN stats for gates, then fold into Y in place
    colstat_stage1<<<dim3(6, 64), 256>>>(pY, H3_, p1s, p1q);
    colstat_stage2<<<6, 256>>>(p1s, p1q, H3_, pG1, pB1, pA1, pC1);
    bnapply_Y<<<(SB_ * (H3_ / 256)), 256>>>();   // 64000*1536/256 = 384000 blocks

    // 4) persistent recurrent scan
    scan2_kernel<<<128, 256, SM_TOT_FLOATS * sizeof(float)>>>();

    // 5) final projection into d_out
    sgemm_kernel<<<dim3((O_ + GBN - 1) / GBN, SB_ / GBM), 256>>>(pH, Wf, out, SB_, O_, H_, O_);

    // 6) BN stats for output
    colstat_stage1<<<dim3(4, 64), 256>>>(out, O_, p2s, p2q);
    colstat_stage2<<<4, 256>>>(p2s, p2q, O_, gf, bf, pA2, pC2);

    // 7) BN-apply + log_softmax in place
    logsoftmax_kernel<<<SB_, 256>>>(out);
}

// round 4
// speedup vs baseline: 2.2648x; 2.2648x over previous
#include <cuda_runtime.h>
#include <math.h>

#define S_   1000
#define B_   64
#define D_   440
#define H_   512
#define O_   1000
#define SB_  64000
#define H3_  1536

// ---------------- scratch ----------------
__device__ __align__(16) float g_Wcat[H3_ * D_];          // packed [Wh;Wz;Wr]
__device__ __align__(16) float g_Y[(size_t)SB_ * H3_];    // raw gate projections
__device__ __align__(16) float g_Hst[(size_t)SB_ * H_];   // all hidden states (b-major rows)
__device__ __align__(16) float g_hT[2][H_ * B_];          // transposed h: [buf][k*64 + b]
__device__ __align__(16) float g_rhT[H_ * B_];            // transposed r*h
__device__ __align__(16) float g_zT[H_ * B_];             // transposed z
__device__ float g_G1[H3_], g_B1[H3_];
__device__ float g_p1s[64 * H3_], g_p1q[64 * H3_];
__device__ float g_A1[H3_], g_C1[H3_];
__device__ float g_p2s[64 * O_], g_p2q[64 * O_];
__device__ float g_A2[O_], g_C2[O_];
__device__ unsigned g_barCount;
__device__ unsigned g_barEpoch;

// ---------------- grid barrier (release/acquire) ----------------
__device__ __forceinline__ void gbar() {
    __syncthreads();
    if (threadIdx.x == 0) {
        unsigned* pc; unsigned* pe;
        asm("cvta.global.u64 %0, %1;" : "=l"(pc) : "l"(&g_barCount));
        asm("cvta.global.u64 %0, %1;" : "=l"(pe) : "l"(&g_barEpoch));
        unsigned e = *((volatile unsigned*)pe);
        unsigned old;
        asm volatile("atom.add.release.gpu.global.u32 %0, [%1], 1;"
                     : "=r"(old) : "l"(pc) : "memory");
        if (old == 127u) {
            asm volatile("st.relaxed.gpu.global.u32 [%0], %1;" :: "l"(pc), "r"(0u) : "memory");
            asm volatile("st.release.gpu.global.u32 [%0], %1;" :: "l"(pe), "r"(e + 1u) : "memory");
        } else {
            unsigned cur;
            do {
                asm volatile("ld.acquire.gpu.global.u32 %0, [%1];"
                             : "=r"(cur) : "l"(pe) : "memory");
            } while (cur == e);
        }
    }
    __syncthreads();
}

// ---------------- packing ----------------
__global__ void pack_w(const float* __restrict__ Wh, const float* __restrict__ Wz,
                       const float* __restrict__ Wr) {
    int i = blockIdx.x * 256 + threadIdx.x;
    int j = i / D_, k = i - j * D_;
    float v = (j < 512) ? Wh[j * D_ + k] : (j < 1024) ? Wz[(j - 512) * D_ + k]
                                                      : Wr[(j - 1024) * D_ + k];
    g_Wcat[i] = v;
}

__global__ void pack_gb(const float* __restrict__ gh, const float* __restrict__ bh,
                        const float* __restrict__ gz, const float* __restrict__ bz,
                        const float* __restrict__ gr, const float* __restrict__ br) {
    int i = blockIdx.x * 256 + threadIdx.x;
    float g, b;
    if (i < 512)      { g = gh[i];        b = bh[i]; }
    else if (i < 1024){ g = gz[i - 512];  b = bz[i - 512]; }
    else              { g = gr[i - 1024]; b = br[i - 1024]; }
    g_G1[i] = g; g_B1[i] = b;
}

// ---------------- fp32 SGEMM: C[M,N] = A[M,K] * Bw[N,K]^T ----------------
#define GBM 128
#define GBN 64
#define GBK 8
__global__ __launch_bounds__(256) void sgemm_kernel(
    const float* __restrict__ A, const float* __restrict__ Bw, float* __restrict__ C,
    int M, int N, int K, int ldc) {
    __shared__ float As[2][GBK][GBM + 4];
    __shared__ float Bs[2][GBK][GBN + 4];
    const int bm = blockIdx.y * GBM;
    const int bn = blockIdx.x * GBN;
    const int t  = threadIdx.x;
    const int tx = t & 15;
    const int ty = t >> 4;
    const int lam = t >> 1, lak = (t & 1) * 4;
    const int lbn = (t & 127) >> 1, lbk = (t & 1) * 4;
    const bool bload = t < 128;

    float acc[8][4];
#pragma unroll
    for (int i = 0; i < 8; i++)
#pragma unroll
        for (int j = 0; j < 4; j++) acc[i][j] = 0.f;

    const int nt = K / GBK;
    float4 va, vb;
    va = *(const float4*)(A + (size_t)(bm + lam) * K + lak);
    vb = make_float4(0.f, 0.f, 0.f, 0.f);
    if (bload && (bn + lbn) < N) vb = *(const float4*)(Bw + (size_t)(bn + lbn) * K + lbk);
    As[0][lak + 0][lam] = va.x; As[0][lak + 1][lam] = va.y;
    As[0][lak + 2][lam] = va.z; As[0][lak + 3][lam] = va.w;
    if (bload) {
        Bs[0][lbk + 0][lbn] = vb.x; Bs[0][lbk + 1][lbn] = vb.y;
        Bs[0][lbk + 2][lbn] = vb.z; Bs[0][lbk + 3][lbn] = vb.w;
    }
    __syncthreads();

    for (int kt = 0; kt < nt; kt++) {
        const int cur = kt & 1;
        const bool has = (kt + 1) < nt;
        if (has) {
            const int k0 = (kt + 1) * GBK;
            va = *(const float4*)(A + (size_t)(bm + lam) * K + k0 + lak);
            vb = make_float4(0.f, 0.f, 0.f, 0.f);
            if (bload && (bn + lbn) < N)
                vb = *(const float4*)(Bw + (size_t)(bn + lbn) * K + k0 + lbk);
        }
#pragma unroll
        for (int k = 0; k < GBK; k++) {
            float a[8], b[4];
#pragma unroll
            for (int i = 0; i < 8; i++) a[i] = As[cur][k][ty * 8 + i];
#pragma unroll
            for (int j = 0; j < 4; j++) b[j] = Bs[cur][k][tx * 4 + j];
#pragma unroll
            for (int i = 0; i < 8; i++)
#pragma unroll
                for (int j = 0; j < 4; j++)
                    acc[i][j] = fmaf(a[i], b[j], acc[i][j]);
        }
        if (has) {
            const int nb = cur ^ 1;
            As[nb][lak + 0][lam] = va.x; As[nb][lak + 1][lam] = va.y;
            As[nb][lak + 2][lam] = va.z; As[nb][lak + 3][lam] = va.w;
            if (bload) {
                Bs[nb][lbk + 0][lbn] = vb.x; Bs[nb][lbk + 1][lbn] = vb.y;
                Bs[nb][lbk + 2][lbn] = vb.z; Bs[nb][lbk + 3][lbn] = vb.w;
            }
        }
        __syncthreads();
    }

#pragma unroll
    for (int i = 0; i < 8; i++) {
        const size_t m = (size_t)(bm + ty * 8 + i);
#pragma unroll
        for (int j = 0; j < 4; j++) {
            const int n = bn + tx * 4 + j;
            if (n < N) C[m * ldc + n] = acc[i][j];
        }
    }
}

// ---------------- deterministic column stats ----------------
__global__ void colstat_stage1(const float* __restrict__ X, int ncols,
                               float* __restrict__ ps, float* __restrict__ pq) {
    const int col = blockIdx.x * 256 + threadIdx.x;
    if (col >= ncols) return;
    const int chunk = blockIdx.y;
    const size_t base = (size_t)chunk * 1000 * ncols + col;
    float s = 0.f, q = 0.f;
    for (int r = 0; r < 1000; r++) {
        const float v = X[base + (size_t)r * ncols];
        s += v; q = fmaf(v, v, q);
    }
    ps[chunk * ncols + col] = s;
    pq[chunk * ncols + col] = q;
}

__global__ void colstat_stage2(const float* __restrict__ ps, const float* __restrict__ pq,
                               int ncols, const float* __restrict__ gamma,
                               const float* __restrict__ beta,
                               float* __restrict__ Aout, float* __restrict__ Cout) {
    const int col = blockIdx.x * 256 + threadIdx.x;
    if (col >= ncols) return;
    float s = 0.f, q = 0.f;
    for (int c = 0; c < 64; c++) { s += ps[c * ncols + col]; q += pq[c * ncols + col]; }
    const float m = s * (1.f / 64000.f);
    const float v = q * (1.f / 64000.f) - m * m;
    const float a = gamma[col] * rsqrtf(v + 1e-5f);
    Aout[col] = a;
    Cout[col] = beta[col] - m * a;
}

// ---------------- persistent scan v3: full-K per CTA, no cross-CTA partials ----------------
// 128 CTAs x 512 threads.
// Phase1: CTA 0..63  -> z for j-slice [cta*8, cta*8+8)   (k=512, split 16 warps x 32k)
//         CTA 64..127-> r, rh for j-slice [(cta-64)*8, +8)
// Phase2: all CTAs   -> hcand + h-update for j-slice [cta*4, cta*4+4)
// smem: sU1[512][8] sU2[512][4] p1[16][8][64] p2[16][4][64] sT[4][64]
#define SMF_U1 0
#define SMF_U2 4096
#define SMF_P1 6144
#define SMF_P2 14336
#define SMF_T  18432
#define SMF_TOT 18752

__global__ __launch_bounds__(512, 1) void scan3_kernel(
    const float* __restrict__ Uh, const float* __restrict__ Uz,
    const float* __restrict__ Ur) {
    extern __shared__ float sm[];
    float* sU1 = sm + SMF_U1;
    float* sU2 = sm + SMF_U2;
    float* sP1 = sm + SMF_P1;
    float* sP2 = sm + SMF_P2;
    float* sT  = sm + SMF_T;

    const int cta  = blockIdx.x;
    const int tid  = threadIdx.x;
    const int w    = tid >> 5;
    const int lane = tid & 31;
    const bool isR = cta >= 64;
    const int jbase1 = (isR ? (cta - 64) : cta) * 8;   // phase1 j-slice base (within 512)
    const int jbase2 = cta * 4;                        // phase2 j-slice base

    // stage U slices (persistent)
    {
        const float* U1 = isR ? Ur : Uz;
        for (int i = tid; i < 4096; i += 512) {        // sU1[k][jj], jj<8
            const int k = i >> 3, jj = i & 7;
            sU1[i] = U1[(jbase1 + jj) * H_ + k];
        }
        for (int i = tid; i < 2048; i += 512) {        // sU2[k][jj], jj<4
            const int k = i >> 2, jj = i & 3;
            sU2[i] = Uh[(jbase2 + jj) * H_ + k];
        }
    }
    // zero h buffer 0 (this CTA's 256-float slice)
    if (tid < 256) g_hT[0][cta * 256 + tid] = 0.f;

    // preload folded-BN coefficients (fixed column per thread)
    float a1g = 0.f, c1g = 0.f;      // phase1 gate col (z: 512+j, r: 1024+j)
    float a1h = 0.f, c1h = 0.f;      // phase2 h col
    {
        const int jj1 = tid >> 6;                       // 0..7
        const int col1 = (isR ? 1024 : 512) + jbase1 + jj1;
        a1g = g_A1[col1]; c1g = g_C1[col1];
        if (tid < 256) {
            const int col2 = jbase2 + (tid >> 6);       // 0..3
            a1h = g_A1[col2]; c1h = g_C1[col2];
        }
    }
    gbar();

    // gemm thread mapping
    const int b4 = (lane & 15) * 4;
    const int j4 = (lane >> 4) * 4;   // phase1: {0,4}
    const int j2 = (lane >> 4) * 2;   // phase2: {0,2}
    const int kw1 = w * 32;           // warp k-slice

    for (int t = 0; t < S_; t++) {
        const int cur = t & 1 ? 1 : 0;  // parity
        const float* hbuf = g_hT[t & 1];
        float* hnext = g_hT[(t + 1) & 1];
        (void)cur;

        // ---- phase1 gemm: partials over warp k-slice ----
        {
            float acc[4][4];
#pragma unroll
            for (int i = 0; i < 4; i++)
#pragma unroll
                for (int j = 0; j < 4; j++) acc[i][j] = 0.f;
#pragma unroll 4
            for (int kk = 0; kk < 32; kk++) {
                const int k = kw1 + kk;
                const float4 hv = __ldcv((const float4*)(hbuf + k * 64 + b4));
                const float4 uv = *(const float4*)(sU1 + k * 8 + j4);
                acc[0][0] = fmaf(hv.x, uv.x, acc[0][0]);
                acc[0][1] = fmaf(hv.x, uv.y, acc[0][1]);
                acc[0][2] = fmaf(hv.x, uv.z, acc[0][2]);
                acc[0][3] = fmaf(hv.x, uv.w, acc[0][3]);
                acc[1][0] = fmaf(hv.y, uv.x, acc[1][0]);
                acc[1][1] = fmaf(hv.y, uv.y, acc[1][1]);
                acc[1][2] = fmaf(hv.y, uv.z, acc[1][2]);
                acc[1][3] = fmaf(hv.y, uv.w, acc[1][3]);
                acc[2][0] = fmaf(hv.z, uv.x, acc[2][0]);
                acc[2][1] = fmaf(hv.z, uv.y, acc[2][1]);
                acc[2][2] = fmaf(hv.z, uv.z, acc[2][2]);
                acc[2][3] = fmaf(hv.z, uv.w, acc[2][3]);
                acc[3][0] = fmaf(hv.w, uv.x, acc[3][0]);
                acc[3][1] = fmaf(hv.w, uv.y, acc[3][1]);
                acc[3][2] = fmaf(hv.w, uv.z, acc[3][2]);
                acc[3][3] = fmaf(hv.w, uv.w, acc[3][3]);
            }
#pragma unroll
            for (int jj = 0; jj < 4; jj++)
                *(float4*)(sP1 + w * 512 + (j4 + jj) * 64 + b4) =
                    make_float4(acc[0][jj], acc[1][jj], acc[2][jj], acc[3][jj]);
        }
        __syncthreads();

        // ---- phase1 reduce + activation -> z or rh (1 output/thread) ----
        {
            const int jj = tid >> 6;            // 0..7
            const int b  = tid & 63;
            float pre = 0.f;
#pragma unroll
            for (int q = 0; q < 16; q++) pre += sP1[q * 512 + jj * 64 + b];
            const int jglob = jbase1 + jj;
            const float yraw = g_Y[((size_t)t * B_ + b) * H3_ +
                                   (isR ? 1024 : 512) + jglob];
            const float gate = 1.f / (1.f + __expf(-(fmaf(yraw, a1g, c1g) + pre)));
            if (isR) {
                const float hv = __ldcv(hbuf + jglob * 64 + b);
                g_rhT[jglob * 64 + b] = gate * hv;
            } else {
                g_zT[jglob * 64 + b] = gate;
            }
        }
        gbar();

        // ---- phase2 gemm: hcand partials over rh ----
        {
            float acc[4][2];
#pragma unroll
            for (int i = 0; i < 4; i++) { acc[i][0] = 0.f; acc[i][1] = 0.f; }
#pragma unroll 4
            for (int kk = 0; kk < 32; kk++) {
                const int k = kw1 + kk;
                const float4 rv = __ldcv((const float4*)(g_rhT + k * 64 + b4));
                const float u0 = sU2[k * 4 + j2];
                const float u1 = sU2[k * 4 + j2 + 1];
                acc[0][0] = fmaf(rv.x, u0, acc[0][0]);
                acc[0][1] = fmaf(rv.x, u1, acc[0][1]);
                acc[1][0] = fmaf(rv.y, u0, acc[1][0]);
                acc[1][1] = fmaf(rv.y, u1, acc[1][1]);
                acc[2][0] = fmaf(rv.z, u0, acc[2][0]);
                acc[2][1] = fmaf(rv.z, u1, acc[2][1]);
                acc[3][0] = fmaf(rv.w, u0, acc[3][0]);
                acc[3][1] = fmaf(rv.w, u1, acc[3][1]);
            }
#pragma unroll
            for (int jj = 0; jj < 2; jj++)
                *(float4*)(sP2 + w * 256 + (j2 + jj) * 64 + b4) =
                    make_float4(acc[0][jj], acc[1][jj], acc[2][jj], acc[3][jj]);
        }
        __syncthreads();

        // ---- phase2 reduce + h update (256 outputs) ----
        if (tid < 256) {
            const int jj = tid >> 6;            // 0..3
            const int b  = tid & 63;
            float pre = 0.f;
#pragma unroll
            for (int q = 0; q < 16; q++) pre += sP2[q * 256 + jj * 64 + b];
            const int jglob = jbase2 + jj;
            const float yraw = g_Y[((size_t)t * B_ + b) * H3_ + jglob];
            const float hc = tanhf(fmaf(yraw, a1h, c1h) + pre);
            const float z  = __ldcv(g_zT + jglob * 64 + b);
            const float hp = __ldcv(hbuf + jglob * 64 + b);
            const float hn = fmaf(z, hp - hc, hc);
            hnext[jglob * 64 + b] = hn;
            sT[jj * 64 + b] = hn;
        }
        __syncthreads();
        if (tid < 64) {
            const float4 v = make_float4(sT[tid], sT[64 + tid], sT[128 + tid], sT[192 + tid]);
            *(float4*)(g_Hst + ((size_t)t * B_ + tid) * H_ + jbase2) = v;
        }
        gbar();
    }
}

// ---------------- row log_softmax with folded BN, in place ----------------
__global__ __launch_bounds__(256) void logsoftmax_kernel(float* __restrict__ C) {
    const int row = blockIdx.x;
    float* p = C + (size_t)row * O_;
    __shared__ float red[256];
    const int t = threadIdx.x;
    float mx = -3.4e38f;
    for (int j = t; j < O_; j += 256) {
        const float v = p[j] * g_A2[j] + g_C2[j];
        mx = fmaxf(mx, v);
    }
    red[t] = mx; __syncthreads();
    for (int s = 128; s > 0; s >>= 1) { if (t < s) red[t] = fmaxf(red[t], red[t + s]); __syncthreads(); }
    mx = red[0]; __syncthreads();
    float sum = 0.f;
    for (int j = t; j < O_; j += 256) {
        const float v = p[j] * g_A2[j] + g_C2[j];
        sum += expf(v - mx);
    }
    red[t] = sum; __syncthreads();
    for (int s = 128; s > 0; s >>= 1) { if (t < s) red[t] += red[t + s]; __syncthreads(); }
    const float lse = mx + logf(red[0]);
    __syncthreads();
    for (int j = t; j < O_; j += 256) {
        const float v = p[j] * g_A2[j] + g_C2[j];
        p[j] = v - lse;
    }
}

// ---------------- launch ----------------
extern "C" void kernel_launch(void* const* d_in, const int* in_sizes, int n_in,
                              void* d_out, int out_size) {
    const float* x  = (const float*)d_in[0];
    const float* Wh = (const float*)d_in[1];
    const float* Wz = (const float*)d_in[2];
    const float* Wr = (const float*)d_in[3];
    const float* Uh = (const float*)d_in[4];
    const float* Uz = (const float*)d_in[5];
    const float* Ur = (const float*)d_in[6];
    const float* gh = (const float*)d_in[7];
    const float* bh = (const float*)d_in[8];
    const float* gz = (const float*)d_in[9];
    const float* bz = (const float*)d_in[10];
    const float* gr = (const float*)d_in[11];
    const float* br = (const float*)d_in[12];
    const float* Wf = (const float*)d_in[13];
    const float* gf = (const float*)d_in[14];
    const float* bf = (const float*)d_in[15];
    float* out = (float*)d_out;

    float *pY, *pH, *pWcat, *p1s, *p1q, *p2s, *p2q, *pG1, *pB1, *pA1, *pC1, *pA2, *pC2;
    cudaGetSymbolAddress((void**)&pY,    g_Y);
    cudaGetSymbolAddress((void**)&pH,    g_Hst);
    cudaGetSymbolAddress((void**)&pWcat, g_Wcat);
    cudaGetSymbolAddress((void**)&p1s,   g_p1s);
    cudaGetSymbolAddress((void**)&p1q,   g_p1q);
    cudaGetSymbolAddress((void**)&p2s,   g_p2s);
    cudaGetSymbolAddress((void**)&p2q,   g_p2q);
    cudaGetSymbolAddress((void**)&pG1,   g_G1);
    cudaGetSymbolAddress((void**)&pB1,   g_B1);
    cudaGetSymbolAddress((void**)&pA1,   g_A1);
    cudaGetSymbolAddress((void**)&pC1,   g_C1);
    cudaGetSymbolAddress((void**)&pA2,   g_A2);
    cudaGetSymbolAddress((void**)&pC2,   g_C2);

    cudaFuncSetAttribute(scan3_kernel, cudaFuncAttributeMaxDynamicSharedMemorySize,
                         SMF_TOT * (int)sizeof(float));

    // 1) pack
    pack_w <<<2640, 256>>>(Wh, Wz, Wr);
    pack_gb<<<6,    256>>>(gh, bh, gz, bz, gr, br);

    // 2) gate projections: Y = x @ Wcat^T
    sgemm_kernel<<<dim3(H3_ / GBN, SB_ / GBM), 256>>>(x, pWcat, pY, SB_, H3_, D_, H3_);

    // 3) BN stats for gates (fold coefficients only; applied inside scan)
    colstat_stage1<<<dim3(6, 64), 256>>>(pY, H3_, p1s, p1q);
    colstat_stage2<<<6, 256>>>(p1s, p1q, H3_, pG1, pB1, pA1, pC1);

    // 4) persistent recurrent scan
    scan3_kernel<<<128, 512, SMF_TOT * sizeof(float)>>>(Uh, Uz, Ur);

    // 5) final projection into d_out
    sgemm_kernel<<<dim3((O_ + GBN - 1) / GBN, SB_ / GBM), 256>>>(pH, Wf, out, SB_, O_, H_, O_);

    // 6) BN stats for output
    colstat_stage1<<<dim3(4, 64), 256>>>(out, O_, p2s, p2q);
    colstat_stage2<<<4, 256>>>(p2s, p2q, O_, gf, bf, pA2, pC2);

    // 7) BN-apply + log_softmax in place
    logsoftmax_kernel<<<SB_, 256>>>(out);
}

// round 5
// speedup vs baseline: 2.4357x; 1.0755x over previous
#include <cuda_runtime.h>
#include <math.h>

#define S_   1000
#define B_   64
#define D_   440
#define H_   512
#define O_   1000
#define SB_  64000
#define H3_  1536

// ---------------- scratch ----------------
__device__ __align__(16) float g_Wcat[H3_ * D_];          // packed [Wh;Wz;Wr]
__device__ __align__(16) float g_Y[(size_t)SB_ * H3_];    // raw gate projections (row-major)
__device__ __align__(16) float g_YT[(size_t)S_ * H3_ * B_]; // BN-folded, transposed: [t][col][b]
__device__ __align__(16) float g_Hst[(size_t)SB_ * H_];   // all hidden states (b-major rows)
__device__ __align__(16) float g_hT[2][H_ * B_];          // transposed h: [buf][k*64 + b]
__device__ __align__(16) float g_rhT[H_ * B_];            // transposed r*h
__device__ __align__(16) float g_zT[H_ * B_];             // transposed z
__device__ float g_G1[H3_], g_B1[H3_];
__device__ float g_p1s[64 * H3_], g_p1q[64 * H3_];
__device__ float g_A1[H3_], g_C1[H3_];
__device__ float g_p2s[64 * O_], g_p2q[64 * O_];
__device__ float g_A2[O_], g_C2[O_];
__device__ unsigned g_barCount;
__device__ unsigned g_barEpoch;

// ---------------- grid barrier (release/acquire) ----------------
__device__ __forceinline__ void gbar() {
    __syncthreads();
    if (threadIdx.x == 0) {
        unsigned* pc; unsigned* pe;
        asm("cvta.global.u64 %0, %1;" : "=l"(pc) : "l"(&g_barCount));
        asm("cvta.global.u64 %0, %1;" : "=l"(pe) : "l"(&g_barEpoch));
        unsigned e = *((volatile unsigned*)pe);
        unsigned old;
        asm volatile("atom.add.release.gpu.global.u32 %0, [%1], 1;"
                     : "=r"(old) : "l"(pc) : "memory");
        if (old == 127u) {
            asm volatile("st.relaxed.gpu.global.u32 [%0], %1;" :: "l"(pc), "r"(0u) : "memory");
            asm volatile("st.release.gpu.global.u32 [%0], %1;" :: "l"(pe), "r"(e + 1u) : "memory");
        } else {
            unsigned cur;
            do {
                asm volatile("ld.acquire.gpu.global.u32 %0, [%1];"
                             : "=r"(cur) : "l"(pe) : "memory");
            } while (cur == e);
        }
    }
    __syncthreads();
}

// ---------------- packing ----------------
__global__ void pack_w(const float* __restrict__ Wh, const float* __restrict__ Wz,
                       const float* __restrict__ Wr) {
    int i = blockIdx.x * 256 + threadIdx.x;
    int j = i / D_, k = i - j * D_;
    float v = (j < 512) ? Wh[j * D_ + k] : (j < 1024) ? Wz[(j - 512) * D_ + k]
                                                      : Wr[(j - 1024) * D_ + k];
    g_Wcat[i] = v;
}

__global__ void pack_gb(const float* __restrict__ gh, const float* __restrict__ bh,
                        const float* __restrict__ gz, const float* __restrict__ bz,
                        const float* __restrict__ gr, const float* __restrict__ br) {
    int i = blockIdx.x * 256 + threadIdx.x;
    float g, b;
    if (i < 512)      { g = gh[i];        b = bh[i]; }
    else if (i < 1024){ g = gz[i - 512];  b = bz[i - 512]; }
    else              { g = gr[i - 1024]; b = br[i - 1024]; }
    g_G1[i] = g; g_B1[i] = b;
}

// ---------------- fp32 SGEMM: C[M,N] = A[M,K] * Bw[N,K]^T ----------------
#define GBM 128
#define GBN 64
#define GBK 8
__global__ __launch_bounds__(256) void sgemm_kernel(
    const float* __restrict__ A, const float* __restrict__ Bw, float* __restrict__ C,
    int M, int N, int K, int ldc) {
    __shared__ float As[2][GBK][GBM + 4];
    __shared__ float Bs[2][GBK][GBN + 4];
    const int bm = blockIdx.y * GBM;
    const int bn = blockIdx.x * GBN;
    const int t  = threadIdx.x;
    const int tx = t & 15;
    const int ty = t >> 4;
    const int lam = t >> 1, lak = (t & 1) * 4;
    const int lbn = (t & 127) >> 1, lbk = (t & 1) * 4;
    const bool bload = t < 128;

    float acc[8][4];
#pragma unroll
    for (int i = 0; i < 8; i++)
#pragma unroll
        for (int j = 0; j < 4; j++) acc[i][j] = 0.f;

    const int nt = K / GBK;
    float4 va, vb;
    va = *(const float4*)(A + (size_t)(bm + lam) * K + lak);
    vb = make_float4(0.f, 0.f, 0.f, 0.f);
    if (bload && (bn + lbn) < N) vb = *(const float4*)(Bw + (size_t)(bn + lbn) * K + lbk);
    As[0][lak + 0][lam] = va.x; As[0][lak + 1][lam] = va.y;
    As[0][lak + 2][lam] = va.z; As[0][lak + 3][lam] = va.w;
    if (bload) {
        Bs[0][lbk + 0][lbn] = vb.x; Bs[0][lbk + 1][lbn] = vb.y;
        Bs[0][lbk + 2][lbn] = vb.z; Bs[0][lbk + 3][lbn] = vb.w;
    }
    __syncthreads();

    for (int kt = 0; kt < nt; kt++) {
        const int cur = kt & 1;
        const bool has = (kt + 1) < nt;
        if (has) {
            const int k0 = (kt + 1) * GBK;
            va = *(const float4*)(A + (size_t)(bm + lam) * K + k0 + lak);
            vb = make_float4(0.f, 0.f, 0.f, 0.f);
            if (bload && (bn + lbn) < N)
                vb = *(const float4*)(Bw + (size_t)(bn + lbn) * K + k0 + lbk);
        }
#pragma unroll
        for (int k = 0; k < GBK; k++) {
            float a[8], b[4];
#pragma unroll
            for (int i = 0; i < 8; i++) a[i] = As[cur][k][ty * 8 + i];
#pragma unroll
            for (int j = 0; j < 4; j++) b[j] = Bs[cur][k][tx * 4 + j];
#pragma unroll
            for (int i = 0; i < 8; i++)
#pragma unroll
                for (int j = 0; j < 4; j++)
                    acc[i][j] = fmaf(a[i], b[j], acc[i][j]);
        }
        if (has) {
            const int nb = cur ^ 1;
            As[nb][lak + 0][lam] = va.x; As[nb][lak + 1][lam] = va.y;
            As[nb][lak + 2][lam] = va.z; As[nb][lak + 3][lam] = va.w;
            if (bload) {
                Bs[nb][lbk + 0][lbn] = vb.x; Bs[nb][lbk + 1][lbn] = vb.y;
                Bs[nb][lbk + 2][lbn] = vb.z; Bs[nb][lbk + 3][lbn] = vb.w;
            }
        }
        __syncthreads();
    }

#pragma unroll
    for (int i = 0; i < 8; i++) {
        const size_t m = (size_t)(bm + ty * 8 + i);
#pragma unroll
        for (int j = 0; j < 4; j++) {
            const int n = bn + tx * 4 + j;
            if (n < N) C[m * ldc + n] = acc[i][j];
        }
    }
}

// ---------------- deterministic column stats ----------------
__global__ void colstat_stage1(const float* __restrict__ X, int ncols,
                               float* __restrict__ ps, float* __restrict__ pq) {
    const int col = blockIdx.x * 256 + threadIdx.x;
    if (col >= ncols) return;
    const int chunk = blockIdx.y;
    const size_t base = (size_t)chunk * 1000 * ncols + col;
    float s = 0.f, q = 0.f;
    for (int r = 0; r < 1000; r++) {
        const float v = X[base + (size_t)r * ncols];
        s += v; q = fmaf(v, v, q);
    }
    ps[chunk * ncols + col] = s;
    pq[chunk * ncols + col] = q;
}

__global__ void colstat_stage2(const float* __restrict__ ps, const float* __restrict__ pq,
                               int ncols, const float* __restrict__ gamma,
                               const float* __restrict__ beta,
                               float* __restrict__ Aout, float* __restrict__ Cout) {
    const int col = blockIdx.x * 256 + threadIdx.x;
    if (col >= ncols) return;
    float s = 0.f, q = 0.f;
    for (int c = 0; c < 64; c++) { s += ps[c * ncols + col]; q += pq[c * ncols + col]; }
    const float m = s * (1.f / 64000.f);
    const float v = q * (1.f / 64000.f) - m * m;
    const float a = gamma[col] * rsqrtf(v + 1e-5f);
    Aout[col] = a;
    Cout[col] = beta[col] - m * a;
}

// ---------------- transpose + BN fold: g_YT[t][col][b] = g_Y[t*64+b][col]*A1+C1 ----------------
__global__ __launch_bounds__(256) void transpose_fold_kernel() {
    __shared__ float tile[32][65];
    const int t    = blockIdx.y;
    const int col0 = blockIdx.x * 32;
    const int tid  = threadIdx.x;
    const int rc = tid & 31;          // col within tile (read)
    const int rb = tid >> 5;          // 8 b-rows per pass
    const float a = g_A1[col0 + rc];
    const float c = g_C1[col0 + rc];
#pragma unroll
    for (int bb = 0; bb < 8; bb++) {
        const int b = rb + bb * 8;
        const float v = g_Y[((size_t)t * B_ + b) * H3_ + col0 + rc];
        tile[rc][b] = fmaf(v, a, c);
    }
    __syncthreads();
    const int wb = tid & 63;          // b (write)
    const int wc = tid >> 6;          // 4 cols per pass
#pragma unroll
    for (int cc = 0; cc < 8; cc++) {
        const int cl = wc + cc * 4;
        g_YT[(size_t)t * (H3_ * B_) + (size_t)(col0 + cl) * B_ + wb] = tile[cl][wb];
    }
}

// ---------------- persistent scan v4: full-K per CTA + coalesced prefetched Y ----------------
// 128 CTAs x 512 threads.
// Phase1: CTA 0..63  -> z for j-slice [cta*8, +8); CTA 64..127 -> r,rh for [(cta-64)*8, +8)
// Phase2: all CTAs   -> hcand + h-update for j-slice [cta*4, +4)
#define SMF_U1 0
#define SMF_U2 4096
#define SMF_P1 6144
#define SMF_P2 14336
#define SMF_T  18432
#define SMF_TOT 18752

__global__ __launch_bounds__(512, 1) void scan4_kernel(
    const float* __restrict__ Uh, const float* __restrict__ Uz,
    const float* __restrict__ Ur) {
    extern __shared__ float sm[];
    float* sU1 = sm + SMF_U1;
    float* sU2 = sm + SMF_U2;
    float* sP1 = sm + SMF_P1;
    float* sP2 = sm + SMF_P2;
    float* sT  = sm + SMF_T;

    const int cta  = blockIdx.x;
    const int tid  = threadIdx.x;
    const int w    = tid >> 5;
    const int lane = tid & 31;
    const bool isR = cta >= 64;
    const int jbase1 = (isR ? (cta - 64) : cta) * 8;
    const int jbase2 = cta * 4;

    // stage U slices (persistent)
    {
        const float* U1 = isR ? Ur : Uz;
        for (int i = tid; i < 4096; i += 512) {
            const int k = i >> 3, jj = i & 7;
            sU1[i] = U1[(jbase1 + jj) * H_ + k];
        }
        for (int i = tid; i < 2048; i += 512) {
            const int k = i >> 2, jj = i & 3;
            sU2[i] = Uh[(jbase2 + jj) * H_ + k];
        }
    }
    if (tid < 256) g_hT[0][cta * 256 + tid] = 0.f;
    gbar();

    // fixed indices for reduce phases
    const int rjj = tid >> 6;                 // 0..7 (phase1)
    const int rb  = tid & 63;
    const int jglob1 = jbase1 + rjj;
    const size_t yoff1 = (size_t)((isR ? 1024 : 512) + jglob1) * B_ + rb;
    const int jglob2 = jbase2 + (rjj & 3);    // phase2 (tid<256)
    const size_t yoff2 = (size_t)jglob2 * B_ + rb;

    // gemm thread mapping
    const int b4 = (lane & 15) * 4;
    const int j4 = (lane >> 4) * 4;
    const int j2 = (lane >> 4) * 2;
    const int kw1 = w * 32;

    for (int t = 0; t < S_; t++) {
        const float* hbuf = g_hT[t & 1];
        float* hnext = g_hT[(t + 1) & 1];
        const float* YTt = g_YT + (size_t)t * (H3_ * B_);

        // ---- prefetch phase1 operands (consumed after the coming syncthreads) ----
        const float yg = __ldcg(YTt + yoff1);
        const float hpre1 = isR ? __ldcv(hbuf + jglob1 * 64 + rb) : 0.f;

        // ---- phase1 gemm: partials over warp k-slice ----
        {
            float acc[4][4];
#pragma unroll
            for (int i = 0; i < 4; i++)
#pragma unroll
                for (int j = 0; j < 4; j++) acc[i][j] = 0.f;
#pragma unroll 4
            for (int kk = 0; kk < 32; kk++) {
                const int k = kw1 + kk;
                const float4 hv = __ldcv((const float4*)(hbuf + k * 64 + b4));
                const float4 uv = *(const float4*)(sU1 + k * 8 + j4);
                acc[0][0] = fmaf(hv.x, uv.x, acc[0][0]);
                acc[0][1] = fmaf(hv.x, uv.y, acc[0][1]);
                acc[0][2] = fmaf(hv.x, uv.z, acc[0][2]);
                acc[0][3] = fmaf(hv.x, uv.w, acc[0][3]);
                acc[1][0] = fmaf(hv.y, uv.x, acc[1][0]);
                acc[1][1] = fmaf(hv.y, uv.y, acc[1][1]);
                acc[1][2] = fmaf(hv.y, uv.z, acc[1][2]);
                acc[1][3] = fmaf(hv.y, uv.w, acc[1][3]);
                acc[2][0] = fmaf(hv.z, uv.x, acc[2][0]);
                acc[2][1] = fmaf(hv.z, uv.y, acc[2][1]);
                acc[2][2] = fmaf(hv.z, uv.z, acc[2][2]);
                acc[2][3] = fmaf(hv.z, uv.w, acc[2][3]);
                acc[3][0] = fmaf(hv.w, uv.x, acc[3][0]);
                acc[3][1] = fmaf(hv.w, uv.y, acc[3][1]);
                acc[3][2] = fmaf(hv.w, uv.z, acc[3][2]);
                acc[3][3] = fmaf(hv.w, uv.w, acc[3][3]);
            }
#pragma unroll
            for (int jj = 0; jj < 4; jj++)
                *(float4*)(sP1 + w * 512 + (j4 + jj) * 64 + b4) =
                    make_float4(acc[0][jj], acc[1][jj], acc[2][jj], acc[3][jj]);
        }
        __syncthreads();

        // ---- phase1 reduce + activation -> z or rh ----
        {
            float pre = 0.f;
#pragma unroll
            for (int q = 0; q < 16; q++) pre += sP1[q * 512 + rjj * 64 + rb];
            const float gate = 1.f / (1.f + __expf(-(yg + pre)));
            if (isR) g_rhT[jglob1 * 64 + rb] = gate * hpre1;
            else     g_zT[jglob1 * 64 + rb] = gate;
        }
        gbar();

        // ---- prefetch phase2 operands ----
        float yh = 0.f, zpre = 0.f, hp2 = 0.f;
        if (tid < 256) {
            yh   = __ldcg(YTt + yoff2);
            zpre = __ldcv(g_zT + jglob2 * 64 + rb);
            hp2  = __ldcv(hbuf + jglob2 * 64 + rb);
        }

        // ---- phase2 gemm: hcand partials over rh ----
        {
            float acc[4][2];
#pragma unroll
            for (int i = 0; i < 4; i++) { acc[i][0] = 0.f; acc[i][1] = 0.f; }
#pragma unroll 4
            for (int kk = 0; kk < 32; kk++) {
                const int k = kw1 + kk;
                const float4 rv = __ldcv((const float4*)(g_rhT + k * 64 + b4));
                const float u0 = sU2[k * 4 + j2];
                const float u1 = sU2[k * 4 + j2 + 1];
                acc[0][0] = fmaf(rv.x, u0, acc[0][0]);
                acc[0][1] = fmaf(rv.x, u1, acc[0][1]);
                acc[1][0] = fmaf(rv.y, u0, acc[1][0]);
                acc[1][1] = fmaf(rv.y, u1, acc[1][1]);
                acc[2][0] = fmaf(rv.z, u0, acc[2][0]);
                acc[2][1] = fmaf(rv.z, u1, acc[2][1]);
                acc[3][0] = fmaf(rv.w, u0, acc[3][0]);
                acc[3][1] = fmaf(rv.w, u1, acc[3][1]);
            }
#pragma unroll
            for (int jj = 0; jj < 2; jj++)
                *(float4*)(sP2 + w * 256 + (j2 + jj) * 64 + b4) =
                    make_float4(acc[0][jj], acc[1][jj], acc[2][jj], acc[3][jj]);
        }
        __syncthreads();

        // ---- phase2 reduce + h update ----
        if (tid < 256) {
            float pre = 0.f;
#pragma unroll
            for (int q = 0; q < 16; q++) pre += sP2[q * 256 + (rjj & 3) * 64 + rb];
            const float hc = tanhf(yh + pre);
            const float hn = fmaf(zpre, hp2 - hc, hc);
            hnext[jglob2 * 64 + rb] = hn;
            sT[(rjj & 3) * 64 + rb] = hn;
        }
        __syncthreads();
        if (tid < 64) {
            const float4 v = make_float4(sT[tid], sT[64 + tid], sT[128 + tid], sT[192 + tid]);
            *(float4*)(g_Hst + ((size_t)t * B_ + tid) * H_ + jbase2) = v;
        }
        gbar();
    }
}

// ---------------- row log_softmax with folded BN, in place ----------------
__global__ __launch_bounds__(256) void logsoftmax_kernel(float* __restrict__ C) {
    const int row = blockIdx.x;
    float* p = C + (size_t)row * O_;
    __shared__ float red[256];
    const int t = threadIdx.x;
    float mx = -3.4e38f;
    for (int j = t; j < O_; j += 256) {
        const float v = p[j] * g_A2[j] + g_C2[j];
        mx = fmaxf(mx, v);
    }
    red[t] = mx; __syncthreads();
    for (int s = 128; s > 0; s >>= 1) { if (t < s) red[t] = fmaxf(red[t], red[t + s]); __syncthreads(); }
    mx = red[0]; __syncthreads();
    float sum = 0.f;
    for (int j = t; j < O_; j += 256) {
        const float v = p[j] * g_A2[j] + g_C2[j];
        sum += expf(v - mx);
    }
    red[t] = sum; __syncthreads();
    for (int s = 128; s > 0; s >>= 1) { if (t < s) red[t] += red[t + s]; __syncthreads(); }
    const float lse = mx + logf(red[0]);
    __syncthreads();
    for (int j = t; j < O_; j += 256) {
        const float v = p[j] * g_A2[j] + g_C2[j];
        p[j] = v - lse;
    }
}

// ---------------- launch ----------------
extern "C" void kernel_launch(void* const* d_in, const int* in_sizes, int n_in,
                              void* d_out, int out_size) {
    const float* x  = (const float*)d_in[0];
    const float* Wh = (const float*)d_in[1];
    const float* Wz = (const float*)d_in[2];
    const float* Wr = (const float*)d_in[3];
    const float* Uh = (const float*)d_in[4];
    const float* Uz = (const float*)d_in[5];
    const float* Ur = (const float*)d_in[6];
    const float* gh = (const float*)d_in[7];
    const float* bh = (const float*)d_in[8];
    const float* gz = (const float*)d_in[9];
    const float* bz = (const float*)d_in[10];
    const float* gr = (const float*)d_in[11];
    const float* br = (const float*)d_in[12];
    const float* Wf = (const float*)d_in[13];
    const float* gf = (const float*)d_in[14];
    const float* bf = (const float*)d_in[15];
    float* out = (float*)d_out;

    float *pY, *pH, *pWcat, *p1s, *p1q, *p2s, *p2q, *pG1, *pB1, *pA1, *pC1, *pA2, *pC2;
    cudaGetSymbolAddress((void**)&pY,    g_Y);
    cudaGetSymbolAddress((void**)&pH,    g_Hst);
    cudaGetSymbolAddress((void**)&pWcat, g_Wcat);
    cudaGetSymbolAddress((void**)&p1s,   g_p1s);
    cudaGetSymbolAddress((void**)&p1q,   g_p1q);
    cudaGetSymbolAddress((void**)&p2s,   g_p2s);
    cudaGetSymbolAddress((void**)&p2q,   g_p2q);
    cudaGetSymbolAddress((void**)&pG1,   g_G1);
    cudaGetSymbolAddress((void**)&pB1,   g_B1);
    cudaGetSymbolAddress((void**)&pA1,   g_A1);
    cudaGetSymbolAddress((void**)&pC1,   g_C1);
    cudaGetSymbolAddress((void**)&pA2,   g_A2);
    cudaGetSymbolAddress((void**)&pC2,   g_C2);

    cudaFuncSetAttribute(scan4_kernel, cudaFuncAttributeMaxDynamicSharedMemorySize,
                         SMF_TOT * (int)sizeof(float));

    // 1) pack
    pack_w <<<2640, 256>>>(Wh, Wz, Wr);
    pack_gb<<<6,    256>>>(gh, bh, gz, bz, gr, br);

    // 2) gate projections: Y = x @ Wcat^T
    sgemm_kernel<<<dim3(H3_ / GBN, SB_ / GBM), 256>>>(x, pWcat, pY, SB_, H3_, D_, H3_);

    // 3) BN stats, then transpose+fold Y -> YT
    colstat_stage1<<<dim3(6, 64), 256>>>(pY, H3_, p1s, p1q);
    colstat_stage2<<<6, 256>>>(p1s, p1q, H3_, pG1, pB1, pA1, pC1);
    transpose_fold_kernel<<<dim3(48, 1000), 256>>>();

    // 4) persistent recurrent scan
    scan4_kernel<<<128, 512, SMF_TOT * sizeof(float)>>>(Uh, Uz, Ur);

    // 5) final projection into d_out
    sgemm_kernel<<<dim3((O_ + GBN - 1) / GBN, SB_ / GBM), 256>>>(pH, Wf, out, SB_, O_, H_, O_);

    // 6) BN stats for output
    colstat_stage1<<<dim3(4, 64), 256>>>(out, O_, p2s, p2q);
    colstat_stage2<<<4, 256>>>(p2s, p2q, O_, gf, bf, pA2, pC2);

    // 7) BN-apply + log_softmax in place
    logsoftmax_kernel<<<SB_, 256>>>(out);
}

// round 6
// speedup vs baseline: 2.5084x; 1.0299x over previous
#include <cuda_runtime.h>
#include <math.h>

#define S_   1000
#define B_   64
#define D_   440
#define H_   512
#define O_   1000
#define SB_  64000
#define H3_  1536

typedef unsigned long long ull;

// ---------------- f32x2 packed helpers ----------------
__device__ __forceinline__ ull pk2(float x, float y) {
    ull r; asm("mov.b64 %0, {%1,%2};" : "=l"(r) : "f"(x), "f"(y)); return r;
}
__device__ __forceinline__ void upk2(ull v, float& x, float& y) {
    asm("mov.b64 {%0,%1}, %2;" : "=f"(x), "=f"(y) : "l"(v));
}
__device__ __forceinline__ ull ffma2(ull a, ull b, ull c) {
    ull d; asm("fma.rn.f32x2 %0, %1, %2, %3;" : "=l"(d) : "l"(a), "l"(b), "l"(c)); return d;
}

// ---------------- scratch ----------------
__device__ __align__(16) float g_Wcat[H3_ * D_];
__device__ __align__(16) float g_Y[(size_t)SB_ * H3_];
__device__ __align__(16) float g_YT[(size_t)S_ * H3_ * B_];  // [t][col][b], BN-folded
__device__ __align__(16) float g_Hst[(size_t)SB_ * H_];
__device__ __align__(16) float g_hT[2][H_ * B_];             // [buf][k*64 + b]
__device__ __align__(16) float g_rhT[H_ * B_];
__device__ __align__(16) float g_zT[H_ * B_];
__device__ float g_G1[H3_], g_B1[H3_];
__device__ float g_p1s[64 * H3_], g_p1q[64 * H3_];
__device__ float g_A1[H3_], g_C1[H3_];
__device__ float g_p2s[64 * O_], g_p2q[64 * O_];
__device__ float g_A2[O_], g_C2[O_];
__device__ unsigned g_barCount;
__device__ unsigned g_barEpoch;

// ---------------- grid barrier ----------------
__device__ __forceinline__ void gbar() {
    __syncthreads();
    if (threadIdx.x == 0) {
        unsigned* pc; unsigned* pe;
        asm("cvta.global.u64 %0, %1;" : "=l"(pc) : "l"(&g_barCount));
        asm("cvta.global.u64 %0, %1;" : "=l"(pe) : "l"(&g_barEpoch));
        unsigned e = *((volatile unsigned*)pe);
        unsigned old;
        asm volatile("atom.add.release.gpu.global.u32 %0, [%1], 1;"
                     : "=r"(old) : "l"(pc) : "memory");
        if (old == 127u) {
            asm volatile("st.relaxed.gpu.global.u32 [%0], %1;" :: "l"(pc), "r"(0u) : "memory");
            asm volatile("st.release.gpu.global.u32 [%0], %1;" :: "l"(pe), "r"(e + 1u) : "memory");
        } else {
            unsigned cur;
            do {
                asm volatile("ld.acquire.gpu.global.u32 %0, [%1];"
                             : "=r"(cur) : "l"(pe) : "memory");
            } while (cur == e);
        }
    }
    __syncthreads();
}

// ---------------- packing ----------------
__global__ void pack_w(const float* __restrict__ Wh, const float* __restrict__ Wz,
                       const float* __restrict__ Wr) {
    int i = blockIdx.x * 256 + threadIdx.x;
    int j = i / D_, k = i - j * D_;
    float v = (j < 512) ? Wh[j * D_ + k] : (j < 1024) ? Wz[(j - 512) * D_ + k]
                                                      : Wr[(j - 1024) * D_ + k];
    g_Wcat[i] = v;
}

__global__ void pack_gb(const float* __restrict__ gh, const float* __restrict__ bh,
                        const float* __restrict__ gz, const float* __restrict__ bz,
                        const float* __restrict__ gr, const float* __restrict__ br) {
    int i = blockIdx.x * 256 + threadIdx.x;
    float g, b;
    if (i < 512)      { g = gh[i];        b = bh[i]; }
    else if (i < 1024){ g = gz[i - 512];  b = bz[i - 512]; }
    else              { g = gr[i - 1024]; b = br[i - 1024]; }
    g_G1[i] = g; g_B1[i] = b;
}

// ---------------- fp32 SGEMM with packed f32x2: C[M,N] = A[M,K] * Bw[N,K]^T ----------------
#define GBM 128
#define GBN 64
#define GBK 8
__global__ __launch_bounds__(256) void sgemm_kernel(
    const float* __restrict__ A, const float* __restrict__ Bw, float* __restrict__ C,
    int M, int N, int K, int ldc) {
    __shared__ float As[2][GBK][GBM + 4];
    __shared__ float Bs[2][GBK][GBN + 4];
    const int bm = blockIdx.y * GBM;
    const int bn = blockIdx.x * GBN;
    const int t  = threadIdx.x;
    const int tx = t & 15;
    const int ty = t >> 4;
    const int lam = t >> 1, lak = (t & 1) * 4;
    const int lbn = (t & 127) >> 1, lbk = (t & 1) * 4;
    const bool bload = t < 128;

    ull acc2[4][4];               // m-pairs (2p,2p+1) x 4 n
#pragma unroll
    for (int p = 0; p < 4; p++)
#pragma unroll
        for (int j = 0; j < 4; j++) acc2[p][j] = 0ull;

    const int nt = K / GBK;
    float4 va, vb;
    va = *(const float4*)(A + (size_t)(bm + lam) * K + lak);
    vb = make_float4(0.f, 0.f, 0.f, 0.f);
    if (bload && (bn + lbn) < N) vb = *(const float4*)(Bw + (size_t)(bn + lbn) * K + lbk);
    As[0][lak + 0][lam] = va.x; As[0][lak + 1][lam] = va.y;
    As[0][lak + 2][lam] = va.z; As[0][lak + 3][lam] = va.w;
    if (bload) {
        Bs[0][lbk + 0][lbn] = vb.x; Bs[0][lbk + 1][lbn] = vb.y;
        Bs[0][lbk + 2][lbn] = vb.z; Bs[0][lbk + 3][lbn] = vb.w;
    }
    __syncthreads();

    for (int kt = 0; kt < nt; kt++) {
        const int cur = kt & 1;
        const bool has = (kt + 1) < nt;
        if (has) {
            const int k0 = (kt + 1) * GBK;
            va = *(const float4*)(A + (size_t)(bm + lam) * K + k0 + lak);
            vb = make_float4(0.f, 0.f, 0.f, 0.f);
            if (bload && (bn + lbn) < N)
                vb = *(const float4*)(Bw + (size_t)(bn + lbn) * K + k0 + lbk);
        }
#pragma unroll
        for (int k = 0; k < GBK; k++) {
            ull a2[4], bb[4];
#pragma unroll
            for (int p = 0; p < 4; p++)
                a2[p] = *(const ull*)&As[cur][k][ty * 8 + 2 * p];
#pragma unroll
            for (int j = 0; j < 4; j++) {
                const float bs = Bs[cur][k][tx * 4 + j];
                bb[j] = pk2(bs, bs);
            }
#pragma unroll
            for (int p = 0; p < 4; p++)
#pragma unroll
                for (int j = 0; j < 4; j++)
                    acc2[p][j] = ffma2(a2[p], bb[j], acc2[p][j]);
        }
        if (has) {
            const int nb = cur ^ 1;
            As[nb][lak + 0][lam] = va.x; As[nb][lak + 1][lam] = va.y;
            As[nb][lak + 2][lam] = va.z; As[nb][lak + 3][lam] = va.w;
            if (bload) {
                Bs[nb][lbk + 0][lbn] = vb.x; Bs[nb][lbk + 1][lbn] = vb.y;
                Bs[nb][lbk + 2][lbn] = vb.z; Bs[nb][lbk + 3][lbn] = vb.w;
            }
        }
        __syncthreads();
    }

#pragma unroll
    for (int p = 0; p < 4; p++) {
        const size_t m0 = (size_t)(bm + ty * 8 + 2 * p);
#pragma unroll
        for (int j = 0; j < 4; j++) {
            const int n = bn + tx * 4 + j;
            if (n < N) {
                float lo, hi;
                upk2(acc2[p][j], lo, hi);
                C[m0 * ldc + n] = lo;
                C[(m0 + 1) * ldc + n] = hi;
            }
        }
    }
}

// ---------------- deterministic column stats ----------------
__global__ void colstat_stage1(const float* __restrict__ X, int ncols,
                               float* __restrict__ ps, float* __restrict__ pq) {
    const int col = blockIdx.x * 256 + threadIdx.x;
    if (col >= ncols) return;
    const int chunk = blockIdx.y;
    const size_t base = (size_t)chunk * 1000 * ncols + col;
    float s = 0.f, q = 0.f;
    for (int r = 0; r < 1000; r++) {
        const float v = X[base + (size_t)r * ncols];
        s += v; q = fmaf(v, v, q);
    }
    ps[chunk * ncols + col] = s;
    pq[chunk * ncols + col] = q;
}

__global__ void colstat_stage2(const float* __restrict__ ps, const float* __restrict__ pq,
                               int ncols, const float* __restrict__ gamma,
                               const float* __restrict__ beta,
                               float* __restrict__ Aout, float* __restrict__ Cout) {
    const int col = blockIdx.x * 256 + threadIdx.x;
    if (col >= ncols) return;
    float s = 0.f, q = 0.f;
    for (int c = 0; c < 64; c++) { s += ps[c * ncols + col]; q += pq[c * ncols + col]; }
    const float m = s * (1.f / 64000.f);
    const float v = q * (1.f / 64000.f) - m * m;
    const float a = gamma[col] * rsqrtf(v + 1e-5f);
    Aout[col] = a;
    Cout[col] = beta[col] - m * a;
}

// ---------------- transpose + BN fold: g_YT[t][col][b] ----------------
__global__ __launch_bounds__(256) void transpose_fold_kernel() {
    __shared__ float tile[32][65];
    const int t    = blockIdx.y;
    const int col0 = blockIdx.x * 32;
    const int tid  = threadIdx.x;
    const int rc = tid & 31;
    const int rb = tid >> 5;
    const float a = g_A1[col0 + rc];
    const float c = g_C1[col0 + rc];
#pragma unroll
    for (int bb = 0; bb < 8; bb++) {
        const int b = rb + bb * 8;
        const float v = g_Y[((size_t)t * B_ + b) * H3_ + col0 + rc];
        tile[rc][b] = fmaf(v, a, c);
    }
    __syncthreads();
    const int wb = tid & 63;
    const int wc = tid >> 6;
#pragma unroll
    for (int cc = 0; cc < 8; cc++) {
        const int cl = wc + cc * 4;
        g_YT[(size_t)t * (H3_ * B_) + (size_t)(col0 + cl) * B_ + wb] = tile[cl][wb];
    }
}

// ---------------- persistent scan v5: b-half split + packed f32x2 ----------------
// 128 CTAs x 512 threads.
// Phase1: cta<64 -> z, cta>=64 -> r/rh. Within group: jt1 = g>>1 (16-j tile), bh = g&1 (b-half).
// Phase2: jt2 = cta>>1 (8-j tile), same bh. Warp = k-slice of 32; lane = local b.
#define SMF_U1 0                    // [512k][16j]  = 8192
#define SMF_U2 8192                 // [512k][8j]   = 4096
#define SMF_P1 12288                // [16w][32b][18] = 9216 (rows padded 16->18)
#define SMF_P2 21504                // [16w][32b][10] = 5120 (rows padded 8->10)
#define SMF_T  26624                // [8j][32b] = 256
#define SMF_TOT 26880

__global__ __launch_bounds__(512, 1) void scan5_kernel(
    const float* __restrict__ Uh, const float* __restrict__ Uz,
    const float* __restrict__ Ur) {
    extern __shared__ float sm[];
    float* sU1 = sm + SMF_U1;
    float* sU2 = sm + SMF_U2;
    float* sP1 = sm + SMF_P1;
    float* sP2 = sm + SMF_P2;
    float* sT  = sm + SMF_T;

    const int cta  = blockIdx.x;
    const int tid  = threadIdx.x;
    const int w    = tid >> 5;
    const int lane = tid & 31;
    const bool isR = cta >= 64;
    const int grp  = isR ? (cta - 64) : cta;
    const int jt1  = grp >> 1;          // 0..31 (16-j tiles)
    const int bh   = cta & 1;           // b-half (same parity both phases)
    const int jt2  = cta >> 1;          // 0..63 (8-j tiles)
    const int bglob = bh * 32 + lane;

    // stage U slices (persistent across all steps)
    {
        const float* U1 = isR ? Ur : Uz;
        for (int i = tid; i < 8192; i += 512) {
            const int k = i >> 4, jj = i & 15;
            sU1[i] = U1[(jt1 * 16 + jj) * H_ + k];
        }
        for (int i = tid; i < 4096; i += 512) {
            const int k = i >> 3, jj = i & 7;
            sU2[i] = Uh[(jt2 * 8 + jj) * H_ + k];
        }
    }
    if (tid < 256) g_hT[0][cta * 256 + tid] = 0.f;
    gbar();

    // reduce-phase indices
    const int rj1 = tid >> 5;                 // 0..15 (phase1 output j)
    const int jglob1 = jt1 * 16 + rj1;
    const size_t yoff1 = (size_t)((isR ? 1024 : 512) + jglob1) * B_ + bglob;
    const int rj2 = (tid >> 5) & 7;           // 0..7 (phase2, tid<256)
    const int jglob2 = jt2 * 8 + rj2;
    const size_t yoff2 = (size_t)jglob2 * B_ + bglob;
    const int kw = w * 32;

    for (int t = 0; t < S_; t++) {
        const float* hbuf = g_hT[t & 1];
        float* hnext = g_hT[(t + 1) & 1];
        const float* YTt = g_YT + (size_t)t * (H3_ * B_);

        // prefetch phase1 operands (consumed after syncthreads)
        const float yg = __ldcg(YTt + yoff1);
        const float hpre1 = isR ? __ldcv(hbuf + jglob1 * 64 + bglob) : 0.f;

        // ---- phase1 gemm: 16 j (paired) x 1 b over warp k-slice ----
        {
            ull acc2[8];
#pragma unroll
            for (int p = 0; p < 8; p++) acc2[p] = 0ull;
#pragma unroll 4
            for (int kk = 0; kk < 32; kk++) {
                const int k = kw + kk;
                const float hv = __ldcv(hbuf + k * 64 + bglob);
                const ull hh = pk2(hv, hv);
                const ull* up = (const ull*)&sU1[k * 16];
#pragma unroll
                for (int p = 0; p < 8; p++) acc2[p] = ffma2(hh, up[p], acc2[p]);
            }
            ull* dst = (ull*)&sP1[w * 576 + lane * 18];
#pragma unroll
            for (int p = 0; p < 8; p++) dst[p] = acc2[p];
        }
        __syncthreads();

        // ---- phase1 reduce + activation -> z or rh ----
        {
            float pre = 0.f;
#pragma unroll
            for (int q = 0; q < 16; q++) pre += sP1[q * 576 + (tid & 31) * 18 + rj1];
            const float gate = 1.f / (1.f + __expf(-(yg + pre)));
            if (isR) g_rhT[jglob1 * 64 + bglob] = gate * hpre1;
            else     g_zT[jglob1 * 64 + bglob] = gate;
        }
        gbar();

        // prefetch phase2 operands
        float yh = 0.f, zv = 0.f, hp2 = 0.f;
        if (tid < 256) {
            yh  = __ldcg(YTt + yoff2);
            zv  = __ldcv(g_zT + jglob2 * 64 + bglob);
            hp2 = __ldcv(hbuf + jglob2 * 64 + bglob);
        }

        // ---- phase2 gemm: 8 j (paired) x 1 b over warp k-slice ----
        {
            ull acc2[4];
#pragma unroll
            for (int p = 0; p < 4; p++) acc2[p] = 0ull;
#pragma unroll 4
            for (int kk = 0; kk < 32; kk++) {
                const int k = kw + kk;
                const float rv = __ldcv(g_rhT + k * 64 + bglob);
                const ull rr = pk2(rv, rv);
                const ull* up = (const ull*)&sU2[k * 8];
#pragma unroll
                for (int p = 0; p < 4; p++) acc2[p] = ffma2(rr, up[p], acc2[p]);
            }
            ull* dst = (ull*)&sP2[w * 320 + lane * 10];
#pragma unroll
            for (int p = 0; p < 4; p++) dst[p] = acc2[p];
        }
        __syncthreads();

        // ---- phase2 reduce + h update ----
        if (tid < 256) {
            float pre = 0.f;
#pragma unroll
            for (int q = 0; q < 16; q++) pre += sP2[q * 320 + (tid & 31) * 10 + rj2];
            const float hc = tanhf(yh + pre);
            const float hn = fmaf(zv, hp2 - hc, hc);
            hnext[jglob2 * 64 + bglob] = hn;
            sT[rj2 * 32 + (tid & 31)] = hn;
        }
        __syncthreads();
        if (tid < 32) {
            const size_t row = (size_t)t * B_ + bh * 32 + tid;
            const float4 v0 = make_float4(sT[0 * 32 + tid], sT[1 * 32 + tid],
                                          sT[2 * 32 + tid], sT[3 * 32 + tid]);
            const float4 v1 = make_float4(sT[4 * 32 + tid], sT[5 * 32 + tid],
                                          sT[6 * 32 + tid], sT[7 * 32 + tid]);
            *(float4*)(g_Hst + row * H_ + jt2 * 8)     = v0;
            *(float4*)(g_Hst + row * H_ + jt2 * 8 + 4) = v1;
        }
        gbar();
    }
}

// ---------------- row log_softmax with folded BN, in place ----------------
__global__ __launch_bounds__(256) void logsoftmax_kernel(float* __restrict__ C) {
    const int row = blockIdx.x;
    float* p = C + (size_t)row * O_;
    __shared__ float red[256];
    const int t = threadIdx.x;
    float mx = -3.4e38f;
    for (int j = t; j < O_; j += 256) {
        const float v = p[j] * g_A2[j] + g_C2[j];
        mx = fmaxf(mx, v);
    }
    red[t] = mx; __syncthreads();
    for (int s = 128; s > 0; s >>= 1) { if (t < s) red[t] = fmaxf(red[t], red[t + s]); __syncthreads(); }
    mx = red[0]; __syncthreads();
    float sum = 0.f;
    for (int j = t; j < O_; j += 256) {
        const float v = p[j] * g_A2[j] + g_C2[j];
        sum += expf(v - mx);
    }
    red[t] = sum; __syncthreads();
    for (int s = 128; s > 0; s >>= 1) { if (t < s) red[t] += red[t + s]; __syncthreads(); }
    const float lse = mx + logf(red[0]);
    __syncthreads();
    for (int j = t; j < O_; j += 256) {
        const float v = p[j] * g_A2[j] + g_C2[j];
        p[j] = v - lse;
    }
}

// ---------------- launch ----------------
extern "C" void kernel_launch(void* const* d_in, const int* in_sizes, int n_in,
                              void* d_out, int out_size) {
    const float* x  = (const float*)d_in[0];
    const float* Wh = (const float*)d_in[1];
    const float* Wz = (const float*)d_in[2];
    const float* Wr = (const float*)d_in[3];
    const float* Uh = (const float*)d_in[4];
    const float* Uz = (const float*)d_in[5];
    const float* Ur = (const float*)d_in[6];
    const float* gh = (const float*)d_in[7];
    const float* bh = (const float*)d_in[8];
    const float* gz = (const float*)d_in[9];
    const float* bz = (const float*)d_in[10];
    const float* gr = (const float*)d_in[11];
    const float* br = (const float*)d_in[12];
    const float* Wf = (const float*)d_in[13];
    const float* gf = (const float*)d_in[14];
    const float* bf = (const float*)d_in[15];
    float* out = (float*)d_out;

    float *pY, *pH, *pWcat, *p1s, *p1q, *p2s, *p2q, *pG1, *pB1, *pA1, *pC1, *pA2, *pC2;
    cudaGetSymbolAddress((void**)&pY,    g_Y);
    cudaGetSymbolAddress((void**)&pH,    g_Hst);
    cudaGetSymbolAddress((void**)&pWcat, g_Wcat);
    cudaGetSymbolAddress((void**)&p1s,   g_p1s);
    cudaGetSymbolAddress((void**)&p1q,   g_p1q);
    cudaGetSymbolAddress((void**)&p2s,   g_p2s);
    cudaGetSymbolAddress((void**)&p2q,   g_p2q);
    cudaGetSymbolAddress((void**)&pG1,   g_G1);
    cudaGetSymbolAddress((void**)&pB1,   g_B1);
    cudaGetSymbolAddress((void**)&pA1,   g_A1);
    cudaGetSymbolAddress((void**)&pC1,   g_C1);
    cudaGetSymbolAddress((void**)&pA2,   g_A2);
    cudaGetSymbolAddress((void**)&pC2,   g_C2);

    cudaFuncSetAttribute(scan5_kernel, cudaFuncAttributeMaxDynamicSharedMemorySize,
                         SMF_TOT * (int)sizeof(float));

    // 1) pack
    pack_w <<<2640, 256>>>(Wh, Wz, Wr);
    pack_gb<<<6,    256>>>(gh, bh, gz, bz, gr, br);

    // 2) gate projections: Y = x @ Wcat^T
    sgemm_kernel<<<dim3(H3_ / GBN, SB_ / GBM), 256>>>(x, pWcat, pY, SB_, H3_, D_, H3_);

    // 3) BN stats, then transpose+fold Y -> YT
    colstat_stage1<<<dim3(6, 64), 256>>>(pY, H3_, p1s, p1q);
    colstat_stage2<<<6, 256>>>(p1s, p1q, H3_, pG1, pB1, pA1, pC1);
    transpose_fold_kernel<<<dim3(48, 1000), 256>>>();

    // 4) persistent recurrent scan
    scan5_kernel<<<128, 512, SMF_TOT * sizeof(float)>>>(Uh, Uz, Ur);

    // 5) final projection into d_out
    sgemm_kernel<<<dim3((O_ + GBN - 1) / GBN, SB_ / GBM), 256>>>(pH, Wf, out, SB_, O_, H_, O_);

    // 6) BN stats for output
    colstat_stage1<<<dim3(4, 64), 256>>>(out, O_, p2s, p2q);
    colstat_stage2<<<4, 256>>>(p2s, p2q, O_, gf, bf, pA2, pC2);

    // 7) BN-apply + log_softmax in place
    logsoftmax_kernel<<<SB_, 256>>>(out);
}

// round 7
// speedup vs baseline: 2.7211x; 1.0848x over previous
#include <cuda_runtime.h>
#include <math.h>

#define S_   1000
#define B_   64
#define D_   440
#define H_   512
#define O_   1000
#define SB_  64000
#define H3_  1536

typedef unsigned long long ull;

// ---------------- f32x2 packed helpers ----------------
__device__ __forceinline__ ull pk2(float x, float y) {
    ull r; asm("mov.b64 %0, {%1,%2};" : "=l"(r) : "f"(x), "f"(y)); return r;
}
__device__ __forceinline__ void upk2(ull v, float& x, float& y) {
    asm("mov.b64 {%0,%1}, %2;" : "=f"(x), "=f"(y) : "l"(v));
}
__device__ __forceinline__ ull ffma2(ull a, ull b, ull c) {
    ull d; asm("fma.rn.f32x2 %0, %1, %2, %3;" : "=l"(d) : "l"(a), "l"(b), "l"(c)); return d;
}

// ---------------- scratch ----------------
__device__ __align__(16) float g_Wcat[H3_ * D_];
__device__ __align__(16) float g_Y[(size_t)SB_ * H3_];
__device__ __align__(16) float g_YT[(size_t)S_ * H3_ * B_];  // [t][col][b], BN-folded
__device__ __align__(16) float g_Hst[(size_t)SB_ * H_];
__device__ __align__(16) float g_hT[2][H_ * B_];             // [buf][k*64 + b]
__device__ __align__(16) float g_rhT[H_ * B_];
__device__ __align__(16) float g_zT[H_ * B_];
__device__ float g_G1[H3_], g_B1[H3_];
__device__ float g_p1s[64 * H3_], g_p1q[64 * H3_];
__device__ float g_A1[H3_], g_C1[H3_];
__device__ float g_p2s[64 * O_], g_p2q[64 * O_];
__device__ float g_A2[O_], g_C2[O_];
__device__ unsigned g_barCount;
__device__ unsigned g_barEpoch;

// ---------------- grid barrier ----------------
__device__ __forceinline__ void gbar() {
    __syncthreads();
    if (threadIdx.x == 0) {
        unsigned* pc; unsigned* pe;
        asm("cvta.global.u64 %0, %1;" : "=l"(pc) : "l"(&g_barCount));
        asm("cvta.global.u64 %0, %1;" : "=l"(pe) : "l"(&g_barEpoch));
        unsigned e = *((volatile unsigned*)pe);
        unsigned old;
        asm volatile("atom.add.release.gpu.global.u32 %0, [%1], 1;"
                     : "=r"(old) : "l"(pc) : "memory");
        if (old == 127u) {
            asm volatile("st.relaxed.gpu.global.u32 [%0], %1;" :: "l"(pc), "r"(0u) : "memory");
            asm volatile("st.release.gpu.global.u32 [%0], %1;" :: "l"(pe), "r"(e + 1u) : "memory");
        } else {
            unsigned cur;
            do {
                asm volatile("ld.acquire.gpu.global.u32 %0, [%1];"
                             : "=r"(cur) : "l"(pe) : "memory");
            } while (cur == e);
        }
    }
    __syncthreads();
}

// ---------------- packing ----------------
__global__ void pack_w(const float* __restrict__ Wh, const float* __restrict__ Wz,
                       const float* __restrict__ Wr) {
    int i = blockIdx.x * 256 + threadIdx.x;
    int j = i / D_, k = i - j * D_;
    float v = (j < 512) ? Wh[j * D_ + k] : (j < 1024) ? Wz[(j - 512) * D_ + k]
                                                      : Wr[(j - 1024) * D_ + k];
    g_Wcat[i] = v;
}

__global__ void pack_gb(const float* __restrict__ gh, const float* __restrict__ bh,
                        const float* __restrict__ gz, const float* __restrict__ bz,
                        const float* __restrict__ gr, const float* __restrict__ br) {
    int i = blockIdx.x * 256 + threadIdx.x;
    float g, b;
    if (i < 512)      { g = gh[i];        b = bh[i]; }
    else if (i < 1024){ g = gz[i - 512];  b = bz[i - 512]; }
    else              { g = gr[i - 1024]; b = br[i - 1024]; }
    g_G1[i] = g; g_B1[i] = b;
}

// ---------------- fp32 SGEMM with packed f32x2 ----------------
#define GBM 128
#define GBN 64
#define GBK 8
__global__ __launch_bounds__(256) void sgemm_kernel(
    const float* __restrict__ A, const float* __restrict__ Bw, float* __restrict__ C,
    int M, int N, int K, int ldc) {
    __shared__ float As[2][GBK][GBM + 4];
    __shared__ float Bs[2][GBK][GBN + 4];
    const int bm = blockIdx.y * GBM;
    const int bn = blockIdx.x * GBN;
    const int t  = threadIdx.x;
    const int tx = t & 15;
    const int ty = t >> 4;
    const int lam = t >> 1, lak = (t & 1) * 4;
    const int lbn = (t & 127) >> 1, lbk = (t & 1) * 4;
    const bool bload = t < 128;

    ull acc2[4][4];
#pragma unroll
    for (int p = 0; p < 4; p++)
#pragma unroll
        for (int j = 0; j < 4; j++) acc2[p][j] = 0ull;

    const int nt = K / GBK;
    float4 va, vb;
    va = *(const float4*)(A + (size_t)(bm + lam) * K + lak);
    vb = make_float4(0.f, 0.f, 0.f, 0.f);
    if (bload && (bn + lbn) < N) vb = *(const float4*)(Bw + (size_t)(bn + lbn) * K + lbk);
    As[0][lak + 0][lam] = va.x; As[0][lak + 1][lam] = va.y;
    As[0][lak + 2][lam] = va.z; As[0][lak + 3][lam] = va.w;
    if (bload) {
        Bs[0][lbk + 0][lbn] = vb.x; Bs[0][lbk + 1][lbn] = vb.y;
        Bs[0][lbk + 2][lbn] = vb.z; Bs[0][lbk + 3][lbn] = vb.w;
    }
    __syncthreads();

    for (int kt = 0; kt < nt; kt++) {
        const int cur = kt & 1;
        const bool has = (kt + 1) < nt;
        if (has) {
            const int k0 = (kt + 1) * GBK;
            va = *(const float4*)(A + (size_t)(bm + lam) * K + k0 + lak);
            vb = make_float4(0.f, 0.f, 0.f, 0.f);
            if (bload && (bn + lbn) < N)
                vb = *(const float4*)(Bw + (size_t)(bn + lbn) * K + k0 + lbk);
        }
#pragma unroll
        for (int k = 0; k < GBK; k++) {
            ull a2[4], bb[4];
#pragma unroll
            for (int p = 0; p < 4; p++)
                a2[p] = *(const ull*)&As[cur][k][ty * 8 + 2 * p];
#pragma unroll
            for (int j = 0; j < 4; j++) {
                const float bs = Bs[cur][k][tx * 4 + j];
                bb[j] = pk2(bs, bs);
            }
#pragma unroll
            for (int p = 0; p < 4; p++)
#pragma unroll
                for (int j = 0; j < 4; j++)
                    acc2[p][j] = ffma2(a2[p], bb[j], acc2[p][j]);
        }
        if (has) {
            const int nb = cur ^ 1;
            As[nb][lak + 0][lam] = va.x; As[nb][lak + 1][lam] = va.y;
            As[nb][lak + 2][lam] = va.z; As[nb][lak + 3][lam] = va.w;
            if (bload) {
                Bs[nb][lbk + 0][lbn] = vb.x; Bs[nb][lbk + 1][lbn] = vb.y;
                Bs[nb][lbk + 2][lbn] = vb.z; Bs[nb][lbk + 3][lbn] = vb.w;
            }
        }
        __syncthreads();
    }

#pragma unroll
    for (int p = 0; p < 4; p++) {
        const size_t m0 = (size_t)(bm + ty * 8 + 2 * p);
#pragma unroll
        for (int j = 0; j < 4; j++) {
            const int n = bn + tx * 4 + j;
            if (n < N) {
                float lo, hi;
                upk2(acc2[p][j], lo, hi);
                C[m0 * ldc + n] = lo;
                C[(m0 + 1) * ldc + n] = hi;
            }
        }
    }
}

// ---------------- deterministic column stats ----------------
__global__ void colstat_stage1(const float* __restrict__ X, int ncols,
                               float* __restrict__ ps, float* __restrict__ pq) {
    const int col = blockIdx.x * 256 + threadIdx.x;
    if (col >= ncols) return;
    const int chunk = blockIdx.y;
    const size_t base = (size_t)chunk * 1000 * ncols + col;
    float s = 0.f, q = 0.f;
    for (int r = 0; r < 1000; r++) {
        const float v = X[base + (size_t)r * ncols];
        s += v; q = fmaf(v, v, q);
    }
    ps[chunk * ncols + col] = s;
    pq[chunk * ncols + col] = q;
}

__global__ void colstat_stage2(const float* __restrict__ ps, const float* __restrict__ pq,
                               int ncols, const float* __restrict__ gamma,
                               const float* __restrict__ beta,
                               float* __restrict__ Aout, float* __restrict__ Cout) {
    const int col = blockIdx.x * 256 + threadIdx.x;
    if (col >= ncols) return;
    float s = 0.f, q = 0.f;
    for (int c = 0; c < 64; c++) { s += ps[c * ncols + col]; q += pq[c * ncols + col]; }
    const float m = s * (1.f / 64000.f);
    const float v = q * (1.f / 64000.f) - m * m;
    const float a = gamma[col] * rsqrtf(v + 1e-5f);
    Aout[col] = a;
    Cout[col] = beta[col] - m * a;
}

// ---------------- transpose + BN fold ----------------
__global__ __launch_bounds__(256) void transpose_fold_kernel() {
    __shared__ float tile[32][65];
    const int t    = blockIdx.y;
    const int col0 = blockIdx.x * 32;
    const int tid  = threadIdx.x;
    const int rc = tid & 31;
    const int rb = tid >> 5;
    const float a = g_A1[col0 + rc];
    const float c = g_C1[col0 + rc];
#pragma unroll
    for (int bb = 0; bb < 8; bb++) {
        const int b = rb + bb * 8;
        const float v = g_Y[((size_t)t * B_ + b) * H3_ + col0 + rc];
        tile[rc][b] = fmaf(v, a, c);
    }
    __syncthreads();
    const int wb = tid & 63;
    const int wc = tid >> 6;
#pragma unroll
    for (int cc = 0; cc < 8; cc++) {
        const int cl = wc + cc * 4;
        g_YT[(size_t)t * (H3_ * B_) + (size_t)(col0 + cl) * B_ + wb] = tile[cl][wb];
    }
}

// ---------------- persistent scan v6: full-unroll MLP32 gemms ----------------
#define SMF_U1 0                    // [512k][16j]  = 8192
#define SMF_U2 8192                 // [512k][8j]   = 4096
#define SMF_P1 12288                // [16w][32b][18] = 9216
#define SMF_P2 21504                // [16w][32b][10] = 5120
#define SMF_T  26624                // [8j][32b] = 256
#define SMF_TOT 26880

__global__ __launch_bounds__(512, 1) void scan6_kernel(
    const float* __restrict__ Uh, const float* __restrict__ Uz,
    const float* __restrict__ Ur) {
    extern __shared__ float sm[];
    float* sU1 = sm + SMF_U1;
    float* sU2 = sm + SMF_U2;
    float* sP1 = sm + SMF_P1;
    float* sP2 = sm + SMF_P2;
    float* sT  = sm + SMF_T;

    const int cta  = blockIdx.x;
    const int tid  = threadIdx.x;
    const int w    = tid >> 5;
    const int lane = tid & 31;
    const bool isR = cta >= 64;
    const int grp  = isR ? (cta - 64) : cta;
    const int jt1  = grp >> 1;
    const int bh   = cta & 1;
    const int jt2  = cta >> 1;
    const int bglob = bh * 32 + lane;

    {
        const float* U1 = isR ? Ur : Uz;
        for (int i = tid; i < 8192; i += 512) {
            const int k = i >> 4, jj = i & 15;
            sU1[i] = U1[(jt1 * 16 + jj) * H_ + k];
        }
        for (int i = tid; i < 4096; i += 512) {
            const int k = i >> 3, jj = i & 7;
            sU2[i] = Uh[(jt2 * 8 + jj) * H_ + k];
        }
    }
    if (tid < 256) g_hT[0][cta * 256 + tid] = 0.f;
    gbar();

    const int rj1 = tid >> 5;
    const int jglob1 = jt1 * 16 + rj1;
    const size_t yoff1 = (size_t)((isR ? 1024 : 512) + jglob1) * B_ + bglob;
    const int rj2 = (tid >> 5) & 7;
    const int jglob2 = jt2 * 8 + rj2;
    const size_t yoff2 = (size_t)jglob2 * B_ + bglob;
    const int kw = w * 32;

    for (int t = 0; t < S_; t++) {
        const float* hbuf = g_hT[t & 1];
        float* hnext = g_hT[(t + 1) & 1];
        const float* YTt = g_YT + (size_t)t * (H3_ * B_);

        // prefetch phase1 operands (consumed after syncthreads)
        const float yg = __ldcg(YTt + yoff1);
        const float hpre1 = isR ? __ldcg(hbuf + jglob1 * 64 + bglob) : 0.f;

        // ---- phase1 gemm: front-batched 32 LDG (full MLP), then FMA sweep ----
        {
            float hr[32];
#pragma unroll
            for (int kk = 0; kk < 32; kk++)
                hr[kk] = __ldcg(hbuf + (kw + kk) * 64 + bglob);
            ull acc2[8];
#pragma unroll
            for (int p = 0; p < 8; p++) acc2[p] = 0ull;
#pragma unroll
            for (int kk = 0; kk < 32; kk++) {
                const ull hh = pk2(hr[kk], hr[kk]);
                const ull* up = (const ull*)&sU1[(kw + kk) * 16];
#pragma unroll
                for (int p = 0; p < 8; p++) acc2[p] = ffma2(hh, up[p], acc2[p]);
            }
            ull* dst = (ull*)&sP1[w * 576 + lane * 18];
#pragma unroll
            for (int p = 0; p < 8; p++) dst[p] = acc2[p];
        }
        __syncthreads();

        // ---- phase1 reduce + activation -> z or rh ----
        {
            float pre = 0.f;
#pragma unroll
            for (int q = 0; q < 16; q++) pre += sP1[q * 576 + (tid & 31) * 18 + rj1];
            const float gate = 1.f / (1.f + __expf(-(yg + pre)));
            if (isR) g_rhT[jglob1 * 64 + bglob] = gate * hpre1;
            else     g_zT[jglob1 * 64 + bglob] = gate;
        }
        gbar();

        // prefetch phase2 operands
        float yh = 0.f, zv = 0.f, hp2 = 0.f;
        if (tid < 256) {
            yh  = __ldcg(YTt + yoff2);
            zv  = __ldcg(g_zT + jglob2 * 64 + bglob);
            hp2 = __ldcg(hbuf + jglob2 * 64 + bglob);
        }

        // ---- phase2 gemm: front-batched 32 LDG, FMA sweep ----
        {
            float rr[32];
#pragma unroll
            for (int kk = 0; kk < 32; kk++)
                rr[kk] = __ldcg(g_rhT + (kw + kk) * 64 + bglob);
            ull acc2[4];
#pragma unroll
            for (int p = 0; p < 4; p++) acc2[p] = 0ull;
#pragma unroll
            for (int kk = 0; kk < 32; kk++) {
                const ull rv = pk2(rr[kk], rr[kk]);
                const ull* up = (const ull*)&sU2[(kw + kk) * 8];
#pragma unroll
                for (int p = 0; p < 4; p++) acc2[p] = ffma2(rv, up[p], acc2[p]);
            }
            ull* dst = (ull*)&sP2[w * 320 + lane * 10];
#pragma unroll
            for (int p = 0; p < 4; p++) dst[p] = acc2[p];
        }
        __syncthreads();

        // ---- phase2 reduce + h update ----
        if (tid < 256) {
            float pre = 0.f;
#pragma unroll
            for (int q = 0; q < 16; q++) pre += sP2[q * 320 + (tid & 31) * 10 + rj2];
            const float hc = tanhf(yh + pre);
            const float hn = fmaf(zv, hp2 - hc, hc);
            hnext[jglob2 * 64 + bglob] = hn;
            sT[rj2 * 32 + (tid & 31)] = hn;
        }
        __syncthreads();
        if (tid < 32) {
            const size_t row = (size_t)t * B_ + bh * 32 + tid;
            const float4 v0 = make_float4(sT[0 * 32 + tid], sT[1 * 32 + tid],
                                          sT[2 * 32 + tid], sT[3 * 32 + tid]);
            const float4 v1 = make_float4(sT[4 * 32 + tid], sT[5 * 32 + tid],
                                          sT[6 * 32 + tid], sT[7 * 32 + tid]);
            *(float4*)(g_Hst + row * H_ + jt2 * 8)     = v0;
            *(float4*)(g_Hst + row * H_ + jt2 * 8 + 4) = v1;
        }
        gbar();
    }
}

// ---------------- row log_softmax with folded BN, in place ----------------
__global__ __launch_bounds__(256) void logsoftmax_kernel(float* __restrict__ C) {
    const int row = blockIdx.x;
    float* p = C + (size_t)row * O_;
    __shared__ float red[256];
    const int t = threadIdx.x;
    float mx = -3.4e38f;
    for (int j = t; j < O_; j += 256) {
        const float v = p[j] * g_A2[j] + g_C2[j];
        mx = fmaxf(mx, v);
    }
    red[t] = mx; __syncthreads();
    for (int s = 128; s > 0; s >>= 1) { if (t < s) red[t] = fmaxf(red[t], red[t + s]); __syncthreads(); }
    mx = red[0]; __syncthreads();
    float sum = 0.f;
    for (int j = t; j < O_; j += 256) {
        const float v = p[j] * g_A2[j] + g_C2[j];
        sum += expf(v - mx);
    }
    red[t] = sum; __syncthreads();
    for (int s = 128; s > 0; s >>= 1) { if (t < s) red[t] += red[t + s]; __syncthreads(); }
    const float lse = mx + logf(red[0]);
    __syncthreads();
    for (int j = t; j < O_; j += 256) {
        const float v = p[j] * g_A2[j] + g_C2[j];
        p[j] = v - lse;
    }
}

// ---------------- launch ----------------
extern "C" void kernel_launch(void* const* d_in, const int* in_sizes, int n_in,
                              void* d_out, int out_size) {
    const float* x  = (const float*)d_in[0];
    const float* Wh = (const float*)d_in[1];
    const float* Wz = (const float*)d_in[2];
    const float* Wr = (const float*)d_in[3];
    const float* Uh = (const float*)d_in[4];
    const float* Uz = (const float*)d_in[5];
    const float* Ur = (const float*)d_in[6];
    const float* gh = (const float*)d_in[7];
    const float* bh = (const float*)d_in[8];
    const float* gz = (const float*)d_in[9];
    const float* bz = (const float*)d_in[10];
    const float* gr = (const float*)d_in[11];
    const float* br = (const float*)d_in[12];
    const float* Wf = (const float*)d_in[13];
    const float* gf = (const float*)d_in[14];
    const float* bf = (const float*)d_in[15];
    float* out = (float*)d_out;

    float *pY, *pH, *pWcat, *p1s, *p1q, *p2s, *p2q, *pG1, *pB1, *pA1, *pC1, *pA2, *pC2;
    cudaGetSymbolAddress((void**)&pY,    g_Y);
    cudaGetSymbolAddress((void**)&pH,    g_Hst);
    cudaGetSymbolAddress((void**)&pWcat, g_Wcat);
    cudaGetSymbolAddress((void**)&p1s,   g_p1s);
    cudaGetSymbolAddress((void**)&p1q,   g_p1q);
    cudaGetSymbolAddress((void**)&p2s,   g_p2s);
    cudaGetSymbolAddress((void**)&p2q,   g_p2q);
    cudaGetSymbolAddress((void**)&pG1,   g_G1);
    cudaGetSymbolAddress((void**)&pB1,   g_B1);
    cudaGetSymbolAddress((void**)&pA1,   g_A1);
    cudaGetSymbolAddress((void**)&pC1,   g_C1);
    cudaGetSymbolAddress((void**)&pA2,   g_A2);
    cudaGetSymbolAddress((void**)&pC2,   g_C2);

    cudaFuncSetAttribute(scan6_kernel, cudaFuncAttributeMaxDynamicSharedMemorySize,
                         SMF_TOT * (int)sizeof(float));

    pack_w <<<2640, 256>>>(Wh, Wz, Wr);
    pack_gb<<<6,    256>>>(gh, bh, gz, bz, gr, br);

    sgemm_kernel<<<dim3(H3_ / GBN, SB_ / GBM), 256>>>(x, pWcat, pY, SB_, H3_, D_, H3_);

    colstat_stage1<<<dim3(6, 64), 256>>>(pY, H3_, p1s, p1q);
    colstat_stage2<<<6, 256>>>(p1s, p1q, H3_, pG1, pB1, pA1, pC1);
    transpose_fold_kernel<<<dim3(48, 1000), 256>>>();

    scan6_kernel<<<128, 512, SMF_TOT * sizeof(float)>>>(Uh, Uz, Ur);

    sgemm_kernel<<<dim3((O_ + GBN - 1) / GBN, SB_ / GBM), 256>>>(pH, Wf, out, SB_, O_, H_, O_);

    colstat_stage1<<<dim3(4, 64), 256>>>(out, O_, p2s, p2q);
    colstat_stage2<<<4, 256>>>(p2s, p2q, O_, gf, bf, pA2, pC2);

    logsoftmax_kernel<<<SB_, 256>>>(out);
}